// round 11
// baseline (speedup 1.0000x reference)
#include <cuda_runtime.h>
#include <cuda_fp16.h>
#include <cstdint>

#define D_MODEL   1024
#define NUM_HEADS 16
#define HEAD_DIM  64
#define D_FF      4096
#define B_        2
#define S_        2048
#define ROWS      (B_ * S_)   // 4096
#define QKV_N     (3 * D_MODEL)

// ---------------------------------------------------------------------------
// Scratch (device globals; no allocation allowed)
// ---------------------------------------------------------------------------
__device__ __half g_xh  [ROWS * D_MODEL];
__device__ __half g_qkv [ROWS * QKV_N];
__device__ __half g_attn[ROWS * D_MODEL];
__device__ float  g_proj[ROWS * D_MODEL];
__device__ float  g_x1  [ROWS * D_MODEL];
__device__ __half g_x1h [ROWS * D_MODEL];
__device__ __half g_ff1 [ROWS * D_FF];
__device__ float  g_ff2 [ROWS * D_MODEL];
__device__ __half g_wqkvt[QKV_N * D_MODEL];
__device__ __half g_wot  [D_MODEL * D_MODEL];
__device__ __half g_w1t  [D_FF * D_MODEL];
__device__ __half g_w2t  [D_MODEL * D_FF];
__device__ float  g_bqkv [QKV_N];

__device__ __forceinline__ uint32_t smem_u32(const void* p) {
    uint32_t a;
    asm("{ .reg .u64 t; cvta.to.shared.u64 t, %1; cvt.u32.u64 %0, t; }"
        : "=r"(a) : "l"(p));
    return a;
}
// fp16 mma m16n8k16, fp32 accum
__device__ __forceinline__ void mma_f16(float* d, const uint32_t* a,
                                        uint32_t b0, uint32_t b1) {
    asm volatile(
        "mma.sync.aligned.m16n8k16.row.col.f32.f16.f16.f32 "
        "{%0,%1,%2,%3}, {%4,%5,%6,%7}, {%8,%9}, {%0,%1,%2,%3};"
        : "+f"(d[0]), "+f"(d[1]), "+f"(d[2]), "+f"(d[3])
        : "r"(a[0]), "r"(a[1]), "r"(a[2]), "r"(a[3]), "r"(b0), "r"(b1));
}
#define LDSM_X4(R0, R1, R2, R3, saddr) \
    asm volatile("ldmatrix.sync.aligned.m8n8.x4.shared.b16 {%0,%1,%2,%3}, [%4];" \
        : "=r"(R0), "=r"(R1), "=r"(R2), "=r"(R3) : "r"(saddr))
#define CP16(dst, src) \
    asm volatile("cp.async.cg.shared.global [%0], [%1], 16;" \
                 :: "r"(dst), "l"(src) : "memory")
#define CP_COMMIT() asm volatile("cp.async.commit_group;" ::: "memory")
#define CP_WAIT1()  asm volatile("cp.async.wait_group 1;" ::: "memory")

__device__ __forceinline__ uint32_t pack_h2(float lo, float hi) {
    __half2 h = __floats2half2_rn(lo, hi);
    return *(uint32_t*)&h;
}

// ---------------------------------------------------------------------------
// Weight prep
// ---------------------------------------------------------------------------
__global__ __launch_bounds__(256)
void transpose3_kernel(const float* __restrict__ wq, const float* __restrict__ wk,
                       const float* __restrict__ wv, __half* __restrict__ out)
{
    __shared__ float t[32][33];
    const float* W = (blockIdx.z == 0) ? wq : (blockIdx.z == 1) ? wk : wv;
    __half* Wt = out + (size_t)blockIdx.z * D_MODEL * D_MODEL;
    const int bn = blockIdx.x * 32;
    const int bk = blockIdx.y * 32;
    const int x = threadIdx.x & 31;
    const int y = (threadIdx.x >> 5) * 4;
    #pragma unroll
    for (int i = 0; i < 4; i++)
        t[y + i][x] = W[(size_t)(bk + y + i) * D_MODEL + bn + x];
    __syncthreads();
    #pragma unroll
    for (int i = 0; i < 4; i++)
        Wt[(size_t)(bn + y + i) * D_MODEL + bk + x] = __float2half(t[x][y + i]);
}

__global__ __launch_bounds__(256)
void transpose_h_kernel(const float* __restrict__ W, __half* __restrict__ Wt,
                        int Kd, int N)
{
    __shared__ float t[32][33];
    const int bn = blockIdx.x * 32;
    const int bk = blockIdx.y * 32;
    const int x = threadIdx.x & 31;
    const int y = (threadIdx.x >> 5) * 4;
    #pragma unroll
    for (int i = 0; i < 4; i++)
        t[y + i][x] = W[(size_t)(bk + y + i) * N + bn + x];
    __syncthreads();
    #pragma unroll
    for (int i = 0; i < 4; i++)
        Wt[(size_t)(bn + y + i) * Kd + bk + x] = __float2half(t[x][y + i]);
}

__global__ __launch_bounds__(256)
void half_copy_kernel(const float* __restrict__ in, __half* __restrict__ out)
{
    const int i = blockIdx.x * 256 + threadIdx.x;
    float4 a = ((const float4*)in)[2 * i];
    float4 b = ((const float4*)in)[2 * i + 1];
    uint4 o;
    o.x = pack_h2(a.x, a.y); o.y = pack_h2(a.z, a.w);
    o.z = pack_h2(b.x, b.y); o.w = pack_h2(b.z, b.w);
    ((uint4*)out)[i] = o;
}

__global__ __launch_bounds__(256)
void pack_bias_kernel(const float* __restrict__ bq, const float* __restrict__ bk,
                      const float* __restrict__ bv, float* __restrict__ o)
{
    const int i = blockIdx.x * 256 + threadIdx.x;
    float v = (i < 1024) ? bq[i] : (i < 2048) ? bk[i - 1024] : bv[i - 2048];
    o[i] = v;
}

// ---------------------------------------------------------------------------
// fp16 mma.sync GEMM, BK=64, ldmatrix, 256 threads (8 warps, 2Mx4N, warp 64x32).
// CTA tile 128x128x64, cp.async double-buffered.
// Dynamic SMEM: 2 stages x 2 operands x (128 x 36 words) = 73728 B; 2 CTAs/SM.
// mode: 0 = f32 out; 1 = ReLU + half out; 2 = half out.
// ---------------------------------------------------------------------------
#define GSTR 36
#define GOP  (128 * GSTR)
#define GEMM_SMEM_BYTES (4 * GOP * 4)   // 73728

__global__ __launch_bounds__(256, 2)
void gemm_f16(const __half* __restrict__ A,
              const __half* __restrict__ Bt,
              const float* __restrict__ bias,
              void* __restrict__ Cv,
              int Kd, int N, int mode)
{
    extern __shared__ uint32_t smg[];
    const uint32_t sbase = smem_u32(smg);

    const int tid  = threadIdx.x;
    const int lane = tid & 31;
    const int wid  = tid >> 5;
    const int g = lane >> 2;
    const int t = lane & 3;
    const int wm = wid & 1;      // M half (64 rows)
    const int wn = wid >> 1;     // N quarter (32 cols)
    const int row0 = blockIdx.y * 128;
    const int col0 = blockIdx.x * 128;

    float acc[4][4][4];
    #pragma unroll
    for (int mi = 0; mi < 4; mi++)
        #pragma unroll
        for (int ni = 0; ni < 4; ni++)
            #pragma unroll
            for (int j = 0; j < 4; j++) acc[mi][ni][j] = 0.f;

    // cp.async mapping: 1024 x 16B per operand per chunk; 256 thr x 4
    uint32_t sdst[4];
    const __half* aP[4];
    const __half* bP[4];
    #pragma unroll
    for (int i = 0; i < 4; i++) {
        const int slot = tid + i * 256;
        const int r = slot >> 3, q = slot & 7;
        sdst[i] = (uint32_t)(r * GSTR + q * 4) * 4u;
        aP[i] = A  + (size_t)(row0 + r) * Kd + q * 8;
        bP[i] = Bt + (size_t)(col0 + r) * Kd + q * 8;
    }

    // ldmatrix per-lane base addresses
    const int lane7 = lane & 7;
    const uint32_t aRow  = (uint32_t)(wm * 64 + lane7 + (lane & 8));
    const uint32_t aColW = (uint32_t)((lane >> 4) * 4);
    const uint32_t aOffB = (aRow * GSTR + aColW) * 4u;
    const uint32_t bRow  = (uint32_t)(wn * 32 + lane7 + ((lane >> 4) & 1) * 8);
    const uint32_t bColW = (uint32_t)(((lane >> 3) & 1) * 4);
    const uint32_t bOffB = (bRow * GSTR + bColW) * 4u + GOP * 4u;

    const int NC = Kd >> 6;

    #pragma unroll
    for (int i = 0; i < 4; i++) {
        CP16(sbase + sdst[i], aP[i]);
        CP16(sbase + GOP * 4u + sdst[i], bP[i]);
    }
    CP_COMMIT();

    for (int c = 0; c < NC; c++) {
        if (c + 1 < NC) {
            const int ko = (c + 1) * 64;
            const uint32_t st = (uint32_t)((c + 1) & 1) * (2u * GOP * 4u);
            #pragma unroll
            for (int i = 0; i < 4; i++) {
                CP16(sbase + st + sdst[i], aP[i] + ko);
                CP16(sbase + st + GOP * 4u + sdst[i], bP[i] + ko);
            }
        }
        CP_COMMIT();
        CP_WAIT1();
        __syncthreads();

        const uint32_t stg = sbase + (uint32_t)(c & 1) * (2u * GOP * 4u);
        const uint32_t aBase = stg + aOffB;
        const uint32_t bBase = stg + bOffB;

        #pragma unroll
        for (int ks = 0; ks < 4; ks++) {
            const uint32_t kOff = (uint32_t)(ks * 8) * 4u;

            uint32_t af[4][4];
            #pragma unroll
            for (int mi = 0; mi < 4; mi++) {
                LDSM_X4(af[mi][0], af[mi][1], af[mi][2], af[mi][3],
                        aBase + (uint32_t)(mi * 16 * GSTR) * 4u + kOff);
            }
            uint32_t bf[4][2];
            #pragma unroll
            for (int pr = 0; pr < 2; pr++) {
                LDSM_X4(bf[2 * pr][0], bf[2 * pr][1], bf[2 * pr + 1][0], bf[2 * pr + 1][1],
                        bBase + (uint32_t)(pr * 16 * GSTR) * 4u + kOff);
            }
            #pragma unroll
            for (int ni = 0; ni < 4; ni++)
                #pragma unroll
                for (int mi = 0; mi < 4; mi++)
                    mma_f16(acc[mi][ni], af[mi], bf[ni][0], bf[ni][1]);
        }
        __syncthreads();
    }

    #pragma unroll
    for (int mi = 0; mi < 4; mi++) {
        const int r0 = row0 + wm * 64 + mi * 16 + g;
        #pragma unroll
        for (int ni = 0; ni < 4; ni++) {
            const int col = col0 + wn * 32 + ni * 8 + 2 * t;
            float2 bb = *(const float2*)&bias[col];
            float v00 = acc[mi][ni][0] + bb.x;
            float v01 = acc[mi][ni][1] + bb.y;
            float v10 = acc[mi][ni][2] + bb.x;
            float v11 = acc[mi][ni][3] + bb.y;
            if (mode == 0) {
                float* C = (float*)Cv;
                float2 o0 = {v00, v01}, o1 = {v10, v11};
                *(float2*)&C[(size_t)r0 * N + col]       = o0;
                *(float2*)&C[(size_t)(r0 + 8) * N + col] = o1;
            } else {
                if (mode == 1) {
                    v00 = fmaxf(v00, 0.f); v01 = fmaxf(v01, 0.f);
                    v10 = fmaxf(v10, 0.f); v11 = fmaxf(v11, 0.f);
                }
                __half* C = (__half*)Cv;
                *(uint32_t*)&C[(size_t)r0 * N + col]       = pack_h2(v00, v01);
                *(uint32_t*)&C[(size_t)(r0 + 8) * N + col] = pack_h2(v10, v11);
            }
        }
    }
}

// ---------------------------------------------------------------------------
// fp16 flash attention (unchanged — proven correct).
// ---------------------------------------------------------------------------
#define ASTR 44
#define VSTR 72

__global__ __launch_bounds__(128)
void attn_f16(const __half* __restrict__ QKV,
              const int*   __restrict__ mask,
              __half* __restrict__ O)
{
    __shared__ uint32_t Qs[64 * ASTR];    // also P staging
    __shared__ uint32_t Ks[64 * ASTR];
    __shared__ uint32_t VT[32 * VSTR];
    __shared__ int ms[64];

    const int b  = blockIdx.z;
    const int h  = blockIdx.y;
    const int q0 = blockIdx.x * 64;
    const int tid  = threadIdx.x;
    const int lane = tid & 31;
    const int wid  = tid >> 5;
    const int g = lane >> 2;
    const int t = lane & 3;

    const int qc = h * HEAD_DIM;
    const int kc = D_MODEL + h * HEAD_DIM;
    const int vc = 2 * D_MODEL + h * HEAD_DIM;

    #pragma unroll
    for (int i = 0; i < 4; i++) {
        const int slot = tid + i * 128;
        const int r = slot >> 3, q8 = slot & 7;
        uint4 v = *(const uint4*)(QKV + (size_t)(b * S_ + q0 + r) * QKV_N + qc + q8 * 8);
        *(uint4*)&Qs[r * ASTR + q8 * 4] = v;
    }
    __syncthreads();

    const int mrow = wid * 16 + g;
    uint32_t qf[4][4];
    #pragma unroll
    for (int ks = 0; ks < 4; ks++) {
        qf[ks][0] = Qs[mrow * ASTR + ks * 8 + t];
        qf[ks][1] = Qs[(mrow + 8) * ASTR + ks * 8 + t];
        qf[ks][2] = Qs[mrow * ASTR + ks * 8 + 4 + t];
        qf[ks][3] = Qs[(mrow + 8) * ASTR + ks * 8 + 4 + t];
    }
    __syncthreads();

    float o[8][4];
    #pragma unroll
    for (int ni = 0; ni < 8; ni++)
        #pragma unroll
        for (int j = 0; j < 4; j++) o[ni][j] = 0.f;
    float m0 = -1e30f, m1 = -1e30f, l0 = 0.f, l1 = 0.f;

    uint32_t* myP = Qs + wid * 16 * ASTR;

    const int vj = tid & 31;
    const int vdh = (tid >> 5) * 16;

    for (int kt = 0; kt < S_; kt += 64) {
        #pragma unroll
        for (int i = 0; i < 4; i++) {
            const int slot = tid + i * 128;
            const int r = slot >> 3, q8 = slot & 7;
            uint4 v = *(const uint4*)(QKV + (size_t)(b * S_ + kt + r) * QKV_N + kc + q8 * 8);
            *(uint4*)&Ks[r * ASTR + q8 * 4] = v;
        }
        {
            const __half* v0p = QKV + (size_t)(b * S_ + kt + 2 * vj) * QKV_N + vc + vdh;
            const __half* v1p = v0p + QKV_N;
            uint4 r0a = *(const uint4*)(v0p);
            uint4 r0b = *(const uint4*)(v0p + 8);
            uint4 r1a = *(const uint4*)(v1p);
            uint4 r1b = *(const uint4*)(v1p + 8);
            uint32_t* dst = &VT[vj * VSTR + vdh];
            uint4 z;
            z.x = __byte_perm(r0a.x, r1a.x, 0x5410);
            z.y = __byte_perm(r0a.x, r1a.x, 0x7632);
            z.z = __byte_perm(r0a.y, r1a.y, 0x5410);
            z.w = __byte_perm(r0a.y, r1a.y, 0x7632);
            *(uint4*)dst = z;
            z.x = __byte_perm(r0a.z, r1a.z, 0x5410);
            z.y = __byte_perm(r0a.z, r1a.z, 0x7632);
            z.z = __byte_perm(r0a.w, r1a.w, 0x5410);
            z.w = __byte_perm(r0a.w, r1a.w, 0x7632);
            *(uint4*)(dst + 4) = z;
            z.x = __byte_perm(r0b.x, r1b.x, 0x5410);
            z.y = __byte_perm(r0b.x, r1b.x, 0x7632);
            z.z = __byte_perm(r0b.y, r1b.y, 0x5410);
            z.w = __byte_perm(r0b.y, r1b.y, 0x7632);
            *(uint4*)(dst + 8) = z;
            z.x = __byte_perm(r0b.z, r1b.z, 0x5410);
            z.y = __byte_perm(r0b.z, r1b.z, 0x7632);
            z.z = __byte_perm(r0b.w, r1b.w, 0x5410);
            z.w = __byte_perm(r0b.w, r1b.w, 0x7632);
            *(uint4*)(dst + 12) = z;
        }
        if (tid < 64) ms[tid] = mask[b * S_ + kt + tid];
        __syncthreads();

        float s[8][4];
        #pragma unroll
        for (int ni = 0; ni < 8; ni++)
            #pragma unroll
            for (int j = 0; j < 4; j++) s[ni][j] = 0.f;

        #pragma unroll
        for (int ks = 0; ks < 4; ks++) {
            #pragma unroll
            for (int ni = 0; ni < 8; ni++) {
                const int n0 = ni * 8 + g;
                const uint32_t b0 = Ks[n0 * ASTR + ks * 8 + t];
                const uint32_t b1 = Ks[n0 * ASTR + ks * 8 + 4 + t];
                mma_f16(s[ni], qf[ks], b0, b1);
            }
        }

        float rmax0 = -1e30f, rmax1 = -1e30f;
        #pragma unroll
        for (int ni = 0; ni < 8; ni++) {
            const int col = ni * 8 + 2 * t;
            const int mz0 = ms[col], mz1 = ms[col + 1];
            float v0 = s[ni][0] * 0.125f; if (mz0 == 0) v0 = -1e9f;
            float v1 = s[ni][1] * 0.125f; if (mz1 == 0) v1 = -1e9f;
            float v2 = s[ni][2] * 0.125f; if (mz0 == 0) v2 = -1e9f;
            float v3 = s[ni][3] * 0.125f; if (mz1 == 0) v3 = -1e9f;
            s[ni][0] = v0; s[ni][1] = v1; s[ni][2] = v2; s[ni][3] = v3;
            rmax0 = fmaxf(rmax0, fmaxf(v0, v1));
            rmax1 = fmaxf(rmax1, fmaxf(v2, v3));
        }
        rmax0 = fmaxf(rmax0, __shfl_xor_sync(0xffffffffu, rmax0, 1));
        rmax0 = fmaxf(rmax0, __shfl_xor_sync(0xffffffffu, rmax0, 2));
        rmax1 = fmaxf(rmax1, __shfl_xor_sync(0xffffffffu, rmax1, 1));
        rmax1 = fmaxf(rmax1, __shfl_xor_sync(0xffffffffu, rmax1, 2));

        const float mn0 = fmaxf(m0, rmax0);
        const float mn1 = fmaxf(m1, rmax1);
        const float c0 = __expf(m0 - mn0);
        const float c1 = __expf(m1 - mn1);

        float rs0 = 0.f, rs1 = 0.f;
        #pragma unroll
        for (int ni = 0; ni < 8; ni++) {
            float p0 = __expf(s[ni][0] - mn0);
            float p1 = __expf(s[ni][1] - mn0);
            float p2 = __expf(s[ni][2] - mn1);
            float p3 = __expf(s[ni][3] - mn1);
            s[ni][0] = p0; s[ni][1] = p1; s[ni][2] = p2; s[ni][3] = p3;
            rs0 += p0 + p1;
            rs1 += p2 + p3;
        }
        rs0 += __shfl_xor_sync(0xffffffffu, rs0, 1);
        rs0 += __shfl_xor_sync(0xffffffffu, rs0, 2);
        rs1 += __shfl_xor_sync(0xffffffffu, rs1, 1);
        rs1 += __shfl_xor_sync(0xffffffffu, rs1, 2);

        l0 = l0 * c0 + rs0;
        l1 = l1 * c1 + rs1;
        #pragma unroll
        for (int ni = 0; ni < 8; ni++) {
            o[ni][0] *= c0; o[ni][1] *= c0;
            o[ni][2] *= c1; o[ni][3] *= c1;
        }
        m0 = mn0; m1 = mn1;

        #pragma unroll
        for (int ni = 0; ni < 8; ni++) {
            myP[g * ASTR + ni * 4 + t]       = pack_h2(s[ni][0], s[ni][1]);
            myP[(g + 8) * ASTR + ni * 4 + t] = pack_h2(s[ni][2], s[ni][3]);
        }
        __syncwarp();

        #pragma unroll
        for (int ks = 0; ks < 4; ks++) {
            uint32_t a[4];
            a[0] = myP[g * ASTR + ks * 8 + t];
            a[1] = myP[(g + 8) * ASTR + ks * 8 + t];
            a[2] = myP[g * ASTR + ks * 8 + 4 + t];
            a[3] = myP[(g + 8) * ASTR + ks * 8 + 4 + t];
            #pragma unroll
            for (int ni = 0; ni < 8; ni++) {
                const uint32_t b0 = VT[(ks * 8 + t) * VSTR + ni * 8 + g];
                const uint32_t b1 = VT[(ks * 8 + 4 + t) * VSTR + ni * 8 + g];
                mma_f16(o[ni], a, b0, b1);
            }
        }
        __syncwarp();
        __syncthreads();
    }

    const float inv0 = 1.f / l0;
    const float inv1 = 1.f / l1;
    const size_t r0 = (size_t)(b * S_ + q0 + mrow) * D_MODEL + h * HEAD_DIM;
    const size_t r1 = (size_t)(b * S_ + q0 + mrow + 8) * D_MODEL + h * HEAD_DIM;
    #pragma unroll
    for (int ni = 0; ni < 8; ni++) {
        const int col = ni * 8 + 2 * t;
        *(uint32_t*)&O[r0 + col] = pack_h2(o[ni][0] * inv0, o[ni][1] * inv0);
        *(uint32_t*)&O[r1 + col] = pack_h2(o[ni][2] * inv1, o[ni][3] * inv1);
    }
}

// ---------------------------------------------------------------------------
// Residual add + LayerNorm; optional fp16 second output
// ---------------------------------------------------------------------------
__global__ __launch_bounds__(256)
void add_ln_kernel(const float* __restrict__ X,
                   const float* __restrict__ Y,
                   const float* __restrict__ g,
                   const float* __restrict__ beta,
                   float* __restrict__ out,
                   __half* __restrict__ outh)
{
    const int row = blockIdx.x;
    const int t = threadIdx.x;
    const float4 a = ((const float4*)(X + (size_t)row * D_MODEL))[t];
    const float4 c = ((const float4*)(Y + (size_t)row * D_MODEL))[t];
    const float v0 = a.x + c.x, v1 = a.y + c.y, v2 = a.z + c.z, v3 = a.w + c.w;

    float s  = v0 + v1 + v2 + v3;
    float ss = v0 * v0 + v1 * v1 + v2 * v2 + v3 * v3;

    #pragma unroll
    for (int off = 16; off; off >>= 1) {
        s  += __shfl_xor_sync(0xffffffffu, s,  off);
        ss += __shfl_xor_sync(0xffffffffu, ss, off);
    }
    __shared__ float ws[8], wss[8];
    const int w = t >> 5;
    if ((t & 31) == 0) { ws[w] = s; wss[w] = ss; }
    __syncthreads();

    float stot = 0.f, sstot = 0.f;
    #pragma unroll
    for (int i = 0; i < 8; i++) { stot += ws[i]; sstot += wss[i]; }

    const float mean = stot * (1.f / 1024.f);
    const float var  = sstot * (1.f / 1024.f) - mean * mean;
    const float r    = rsqrtf(var + 1e-5f);

    const float4 gg = ((const float4*)g)[t];
    const float4 bb = ((const float4*)beta)[t];
    float4 o;
    o.x = (v0 - mean) * r * gg.x + bb.x;
    o.y = (v1 - mean) * r * gg.y + bb.y;
    o.z = (v2 - mean) * r * gg.z + bb.z;
    o.w = (v3 - mean) * r * gg.w + bb.w;
    ((float4*)(out + (size_t)row * D_MODEL))[t] = o;
    if (outh) {
        uint2 q;
        q.x = pack_h2(o.x, o.y);
        q.y = pack_h2(o.z, o.w);
        ((uint2*)(outh + (size_t)row * D_MODEL))[t] = q;
    }
}

// ---------------------------------------------------------------------------
// Launch — QKV GEMM in profiled slot #4
// ---------------------------------------------------------------------------
extern "C" void kernel_launch(void* const* d_in, const int* in_sizes, int n_in,
                              void* d_out, int out_size)
{
    const float* x    = (const float*)d_in[0];
    const int*   mask = (const int*)  d_in[1];
    const float* wq   = (const float*)d_in[2];
    const float* bq   = (const float*)d_in[3];
    const float* wk   = (const float*)d_in[4];
    const float* bk   = (const float*)d_in[5];
    const float* wv   = (const float*)d_in[6];
    const float* bv   = (const float*)d_in[7];
    const float* wo   = (const float*)d_in[8];
    const float* bo   = (const float*)d_in[9];
    const float* w1   = (const float*)d_in[10];
    const float* b1   = (const float*)d_in[11];
    const float* w2   = (const float*)d_in[12];
    const float* b2   = (const float*)d_in[13];
    const float* ln1g = (const float*)d_in[14];
    const float* ln1b = (const float*)d_in[15];
    const float* ln2g = (const float*)d_in[16];
    const float* ln2b = (const float*)d_in[17];

    __half *xh, *qkv, *ap, *x1h, *f1p;
    float *pp, *x1p, *f2p, *bqkv;
    __half *wqkvt, *wot, *w1t, *w2t;
    cudaGetSymbolAddress((void**)&xh,    g_xh);
    cudaGetSymbolAddress((void**)&qkv,   g_qkv);
    cudaGetSymbolAddress((void**)&ap,    g_attn);
    cudaGetSymbolAddress((void**)&pp,    g_proj);
    cudaGetSymbolAddress((void**)&x1p,   g_x1);
    cudaGetSymbolAddress((void**)&x1h,   g_x1h);
    cudaGetSymbolAddress((void**)&f1p,   g_ff1);
    cudaGetSymbolAddress((void**)&f2p,   g_ff2);
    cudaGetSymbolAddress((void**)&wqkvt, g_wqkvt);
    cudaGetSymbolAddress((void**)&wot,   g_wot);
    cudaGetSymbolAddress((void**)&w1t,   g_w1t);
    cudaGetSymbolAddress((void**)&w2t,   g_w2t);
    cudaGetSymbolAddress((void**)&bqkv,  g_bqkv);

    static int attr_set = 0;
    if (!attr_set) {
        cudaFuncSetAttribute(gemm_f16,
                             cudaFuncAttributeMaxDynamicSharedMemorySize,
                             GEMM_SMEM_BYTES);
        cudaFuncSetAttribute(gemm_f16,
                             cudaFuncAttributePreferredSharedMemoryCarveout,
                             cudaSharedmemCarveoutMaxShared);
        attr_set = 1;
    }

    // 1-3: QKV GEMM dependencies
    transpose3_kernel<<<dim3(32, 32, 3), 256>>>(wq, wk, wv, wqkvt);
    pack_bias_kernel<<<QKV_N / 256, 256>>>(bq, bk, bv, bqkv);
    half_copy_kernel<<<ROWS * D_MODEL / 8 / 256, 256>>>(x, xh);

    // 4 (profiled): fused QKV GEMM
    gemm_f16<<<dim3(QKV_N / 128, ROWS / 128), 256, GEMM_SMEM_BYTES>>>(
        xh, wqkvt, bqkv, qkv, D_MODEL, QKV_N, 2);

    transpose_h_kernel<<<dim3(D_MODEL / 32, D_MODEL / 32), 256>>>(wo, wot, D_MODEL, D_MODEL);
    transpose_h_kernel<<<dim3(D_FF / 32,    D_MODEL / 32), 256>>>(w1, w1t, D_MODEL, D_FF);
    transpose_h_kernel<<<dim3(D_MODEL / 32, D_FF / 32),    256>>>(w2, w2t, D_FF, D_MODEL);

    attn_f16<<<dim3(S_ / 64, NUM_HEADS, B_), 128>>>(qkv, mask, ap);

    gemm_f16<<<dim3(D_MODEL / 128, ROWS / 128), 256, GEMM_SMEM_BYTES>>>(
        ap, wot, bo, pp, D_MODEL, D_MODEL, 0);
    add_ln_kernel<<<ROWS, 256>>>(x, pp, ln1g, ln1b, x1p, x1h);

    gemm_f16<<<dim3(D_FF / 128, ROWS / 128), 256, GEMM_SMEM_BYTES>>>(
        x1h, w1t, b1, f1p, D_MODEL, D_FF, 1);
    gemm_f16<<<dim3(D_MODEL / 128, ROWS / 128), 256, GEMM_SMEM_BYTES>>>(
        f1p, w2t, b2, f2p, D_FF, D_MODEL, 0);
    add_ln_kernel<<<ROWS, 256>>>(x1p, f2p, ln2g, ln2b, (float*)d_out, (__half*)0);
}

// round 12
// speedup vs baseline: 1.4724x; 1.4724x over previous
#include <cuda_runtime.h>
#include <cuda_fp16.h>
#include <cstdint>

#define D_MODEL   1024
#define NUM_HEADS 16
#define HEAD_DIM  64
#define D_FF      4096
#define B_        2
#define S_        2048
#define ROWS      (B_ * S_)   // 4096
#define QKV_N     (3 * D_MODEL)

// ---------------------------------------------------------------------------
// Scratch (device globals; no allocation allowed)
// ---------------------------------------------------------------------------
__device__ __half g_xh  [ROWS * D_MODEL];
__device__ __half g_qkv [ROWS * QKV_N];
__device__ __half g_attn[ROWS * D_MODEL];
__device__ float  g_proj[ROWS * D_MODEL];
__device__ float  g_x1  [ROWS * D_MODEL];
__device__ __half g_x1h [ROWS * D_MODEL];
__device__ __half g_ff1 [ROWS * D_FF];
__device__ float  g_ff2 [ROWS * D_MODEL];
__device__ __half g_wqkvt[QKV_N * D_MODEL];
__device__ __half g_wot  [D_MODEL * D_MODEL];
__device__ __half g_w1t  [D_FF * D_MODEL];
__device__ __half g_w2t  [D_MODEL * D_FF];
__device__ float  g_bqkv [QKV_N];

__device__ __forceinline__ uint32_t smem_u32(const void* p) {
    uint32_t a;
    asm("{ .reg .u64 t; cvta.to.shared.u64 t, %1; cvt.u32.u64 %0, t; }"
        : "=r"(a) : "l"(p));
    return a;
}
// fp16 mma m16n8k16, fp32 accum
__device__ __forceinline__ void mma_f16(float* d, const uint32_t* a,
                                        uint32_t b0, uint32_t b1) {
    asm volatile(
        "mma.sync.aligned.m16n8k16.row.col.f32.f16.f16.f32 "
        "{%0,%1,%2,%3}, {%4,%5,%6,%7}, {%8,%9}, {%0,%1,%2,%3};"
        : "+f"(d[0]), "+f"(d[1]), "+f"(d[2]), "+f"(d[3])
        : "r"(a[0]), "r"(a[1]), "r"(a[2]), "r"(a[3]), "r"(b0), "r"(b1));
}
#define LDSM_X4(R0, R1, R2, R3, saddr) \
    asm volatile("ldmatrix.sync.aligned.m8n8.x4.shared.b16 {%0,%1,%2,%3}, [%4];" \
        : "=r"(R0), "=r"(R1), "=r"(R2), "=r"(R3) : "r"(saddr))
#define CP16(dst, src) \
    asm volatile("cp.async.cg.shared.global [%0], [%1], 16;" \
                 :: "r"(dst), "l"(src) : "memory")
#define CP_COMMIT() asm volatile("cp.async.commit_group;" ::: "memory")
#define CP_WAIT1()  asm volatile("cp.async.wait_group 1;" ::: "memory")

__device__ __forceinline__ uint32_t pack_h2(float lo, float hi) {
    __half2 h = __floats2half2_rn(lo, hi);
    return *(uint32_t*)&h;
}

// ---------------------------------------------------------------------------
// Weight prep
// ---------------------------------------------------------------------------
__global__ __launch_bounds__(256)
void transpose3_kernel(const float* __restrict__ wq, const float* __restrict__ wk,
                       const float* __restrict__ wv, __half* __restrict__ out)
{
    __shared__ float t[32][33];
    const float* W = (blockIdx.z == 0) ? wq : (blockIdx.z == 1) ? wk : wv;
    __half* Wt = out + (size_t)blockIdx.z * D_MODEL * D_MODEL;
    const int bn = blockIdx.x * 32;
    const int bk = blockIdx.y * 32;
    const int x = threadIdx.x & 31;
    const int y = (threadIdx.x >> 5) * 4;
    #pragma unroll
    for (int i = 0; i < 4; i++)
        t[y + i][x] = W[(size_t)(bk + y + i) * D_MODEL + bn + x];
    __syncthreads();
    #pragma unroll
    for (int i = 0; i < 4; i++)
        Wt[(size_t)(bn + y + i) * D_MODEL + bk + x] = __float2half(t[x][y + i]);
}

__global__ __launch_bounds__(256)
void transpose_h_kernel(const float* __restrict__ W, __half* __restrict__ Wt,
                        int Kd, int N)
{
    __shared__ float t[32][33];
    const int bn = blockIdx.x * 32;
    const int bk = blockIdx.y * 32;
    const int x = threadIdx.x & 31;
    const int y = (threadIdx.x >> 5) * 4;
    #pragma unroll
    for (int i = 0; i < 4; i++)
        t[y + i][x] = W[(size_t)(bk + y + i) * N + bn + x];
    __syncthreads();
    #pragma unroll
    for (int i = 0; i < 4; i++)
        Wt[(size_t)(bn + y + i) * Kd + bk + x] = __float2half(t[x][y + i]);
}

__global__ __launch_bounds__(256)
void half_copy_kernel(const float* __restrict__ in, __half* __restrict__ out)
{
    const int i = blockIdx.x * 256 + threadIdx.x;
    float4 a = ((const float4*)in)[2 * i];
    float4 b = ((const float4*)in)[2 * i + 1];
    uint4 o;
    o.x = pack_h2(a.x, a.y); o.y = pack_h2(a.z, a.w);
    o.z = pack_h2(b.x, b.y); o.w = pack_h2(b.z, b.w);
    ((uint4*)out)[i] = o;
}

__global__ __launch_bounds__(256)
void pack_bias_kernel(const float* __restrict__ bq, const float* __restrict__ bk,
                      const float* __restrict__ bv, float* __restrict__ o)
{
    const int i = blockIdx.x * 256 + threadIdx.x;
    float v = (i < 1024) ? bq[i] : (i < 2048) ? bk[i - 1024] : bv[i - 2048];
    o[i] = v;
}

// ---------------------------------------------------------------------------
// fp16 mma.sync GEMM, BK=64, ldmatrix + register double-buffered fragments.
// CTA 128x128x64, 4 warps (2Mx2N, warp 64x64), cp.async double-buffered.
// Dynamic SMEM: 73728 B; 2 CTAs/SM (reg-limited).
// mode: 0 = f32 out; 1 = ReLU + half out; 2 = half out.
// ---------------------------------------------------------------------------
#define GSTR 36
#define GOP  (128 * GSTR)
#define GEMM_SMEM_BYTES (4 * GOP * 4)   // 73728

__global__ __launch_bounds__(128)
void gemm_f16(const __half* __restrict__ A,
              const __half* __restrict__ Bt,
              const float* __restrict__ bias,
              void* __restrict__ Cv,
              int Kd, int N, int mode)
{
    extern __shared__ uint32_t smg[];
    const uint32_t sbase = smem_u32(smg);

    const int tid  = threadIdx.x;
    const int lane = tid & 31;
    const int wid  = tid >> 5;
    const int g = lane >> 2;
    const int t = lane & 3;
    const int wm = wid & 1;
    const int wn = wid >> 1;
    const int row0 = blockIdx.y * 128;
    const int col0 = blockIdx.x * 128;

    float acc[4][8][4];
    #pragma unroll
    for (int mi = 0; mi < 4; mi++)
        #pragma unroll
        for (int ni = 0; ni < 8; ni++)
            #pragma unroll
            for (int j = 0; j < 4; j++) acc[mi][ni][j] = 0.f;

    // cp.async mapping: 1024 x 16B per operand per chunk; 128 thr x 8
    uint32_t sdst[8];
    const __half* aP[8];
    const __half* bP[8];
    #pragma unroll
    for (int i = 0; i < 8; i++) {
        const int slot = tid + i * 128;
        const int r = slot >> 3, q = slot & 7;
        sdst[i] = (uint32_t)(r * GSTR + q * 4) * 4u;
        aP[i] = A  + (size_t)(row0 + r) * Kd + q * 8;
        bP[i] = Bt + (size_t)(col0 + r) * Kd + q * 8;
    }

    // ldmatrix per-lane base addresses (byte offsets within a stage)
    const int lane7 = lane & 7;
    const uint32_t aRow  = (uint32_t)(wm * 64 + lane7 + (lane & 8));
    const uint32_t aColW = (uint32_t)((lane >> 4) * 4);
    const uint32_t aOffB = (aRow * GSTR + aColW) * 4u;
    const uint32_t bRow  = (uint32_t)(wn * 64 + lane7 + ((lane >> 4) & 1) * 8);
    const uint32_t bColW = (uint32_t)(((lane >> 3) & 1) * 4);
    const uint32_t bOffB = (bRow * GSTR + bColW) * 4u + GOP * 4u;

    const int NC = Kd >> 6;

    #pragma unroll
    for (int i = 0; i < 8; i++) {
        CP16(sbase + sdst[i], aP[i]);
        CP16(sbase + GOP * 4u + sdst[i], bP[i]);
    }
    CP_COMMIT();

    for (int c = 0; c < NC; c++) {
        if (c + 1 < NC) {
            const int ko = (c + 1) * 64;
            const uint32_t st = (uint32_t)((c + 1) & 1) * (2u * GOP * 4u);
            #pragma unroll
            for (int i = 0; i < 8; i++) {
                CP16(sbase + st + sdst[i], aP[i] + ko);
                CP16(sbase + st + GOP * 4u + sdst[i], bP[i] + ko);
            }
        }
        CP_COMMIT();
        CP_WAIT1();
        __syncthreads();

        const uint32_t stg = sbase + (uint32_t)(c & 1) * (2u * GOP * 4u);
        const uint32_t aBase = stg + aOffB;
        const uint32_t bBase = stg + bOffB;

        // Register double-buffered fragments: load ks+1 while mma'ing ks.
        uint32_t af[2][4][4];
        uint32_t bf[2][8][2];
        #pragma unroll
        for (int mi = 0; mi < 4; mi++)
            LDSM_X4(af[0][mi][0], af[0][mi][1], af[0][mi][2], af[0][mi][3],
                    aBase + (uint32_t)(mi * 16 * GSTR) * 4u);
        #pragma unroll
        for (int pr = 0; pr < 4; pr++)
            LDSM_X4(bf[0][2 * pr][0], bf[0][2 * pr][1],
                    bf[0][2 * pr + 1][0], bf[0][2 * pr + 1][1],
                    bBase + (uint32_t)(pr * 16 * GSTR) * 4u);

        #pragma unroll
        for (int ks = 0; ks < 4; ks++) {
            const int cur = ks & 1;
            const int nxt = cur ^ 1;
            if (ks < 3) {
                const uint32_t kOff = (uint32_t)((ks + 1) * 8) * 4u;
                #pragma unroll
                for (int mi = 0; mi < 4; mi++)
                    LDSM_X4(af[nxt][mi][0], af[nxt][mi][1],
                            af[nxt][mi][2], af[nxt][mi][3],
                            aBase + (uint32_t)(mi * 16 * GSTR) * 4u + kOff);
                #pragma unroll
                for (int pr = 0; pr < 4; pr++)
                    LDSM_X4(bf[nxt][2 * pr][0], bf[nxt][2 * pr][1],
                            bf[nxt][2 * pr + 1][0], bf[nxt][2 * pr + 1][1],
                            bBase + (uint32_t)(pr * 16 * GSTR) * 4u + kOff);
            }
            #pragma unroll
            for (int ni = 0; ni < 8; ni++)
                #pragma unroll
                for (int mi = 0; mi < 4; mi++)
                    mma_f16(acc[mi][ni], af[cur][mi], bf[cur][ni][0], bf[cur][ni][1]);
        }
        __syncthreads();
    }

    #pragma unroll
    for (int mi = 0; mi < 4; mi++) {
        const int r0 = row0 + wm * 64 + mi * 16 + g;
        #pragma unroll
        for (int ni = 0; ni < 8; ni++) {
            const int col = col0 + wn * 64 + ni * 8 + 2 * t;
            float2 bb = *(const float2*)&bias[col];
            float v00 = acc[mi][ni][0] + bb.x;
            float v01 = acc[mi][ni][1] + bb.y;
            float v10 = acc[mi][ni][2] + bb.x;
            float v11 = acc[mi][ni][3] + bb.y;
            if (mode == 0) {
                float* C = (float*)Cv;
                float2 o0 = {v00, v01}, o1 = {v10, v11};
                *(float2*)&C[(size_t)r0 * N + col]       = o0;
                *(float2*)&C[(size_t)(r0 + 8) * N + col] = o1;
            } else {
                if (mode == 1) {
                    v00 = fmaxf(v00, 0.f); v01 = fmaxf(v01, 0.f);
                    v10 = fmaxf(v10, 0.f); v11 = fmaxf(v11, 0.f);
                }
                __half* C = (__half*)Cv;
                *(uint32_t*)&C[(size_t)r0 * N + col]       = pack_h2(v00, v01);
                *(uint32_t*)&C[(size_t)(r0 + 8) * N + col] = pack_h2(v10, v11);
            }
        }
    }
}

// ---------------------------------------------------------------------------
// fp16 flash attention (unchanged — proven correct).
// ---------------------------------------------------------------------------
#define ASTR 44
#define VSTR 72

__global__ __launch_bounds__(128)
void attn_f16(const __half* __restrict__ QKV,
              const int*   __restrict__ mask,
              __half* __restrict__ O)
{
    __shared__ uint32_t Qs[64 * ASTR];    // also P staging
    __shared__ uint32_t Ks[64 * ASTR];
    __shared__ uint32_t VT[32 * VSTR];
    __shared__ int ms[64];

    const int b  = blockIdx.z;
    const int h  = blockIdx.y;
    const int q0 = blockIdx.x * 64;
    const int tid  = threadIdx.x;
    const int lane = tid & 31;
    const int wid  = tid >> 5;
    const int g = lane >> 2;
    const int t = lane & 3;

    const int qc = h * HEAD_DIM;
    const int kc = D_MODEL + h * HEAD_DIM;
    const int vc = 2 * D_MODEL + h * HEAD_DIM;

    #pragma unroll
    for (int i = 0; i < 4; i++) {
        const int slot = tid + i * 128;
        const int r = slot >> 3, q8 = slot & 7;
        uint4 v = *(const uint4*)(QKV + (size_t)(b * S_ + q0 + r) * QKV_N + qc + q8 * 8);
        *(uint4*)&Qs[r * ASTR + q8 * 4] = v;
    }
    __syncthreads();

    const int mrow = wid * 16 + g;
    uint32_t qf[4][4];
    #pragma unroll
    for (int ks = 0; ks < 4; ks++) {
        qf[ks][0] = Qs[mrow * ASTR + ks * 8 + t];
        qf[ks][1] = Qs[(mrow + 8) * ASTR + ks * 8 + t];
        qf[ks][2] = Qs[mrow * ASTR + ks * 8 + 4 + t];
        qf[ks][3] = Qs[(mrow + 8) * ASTR + ks * 8 + 4 + t];
    }
    __syncthreads();

    float o[8][4];
    #pragma unroll
    for (int ni = 0; ni < 8; ni++)
        #pragma unroll
        for (int j = 0; j < 4; j++) o[ni][j] = 0.f;
    float m0 = -1e30f, m1 = -1e30f, l0 = 0.f, l1 = 0.f;

    uint32_t* myP = Qs + wid * 16 * ASTR;

    const int vj = tid & 31;
    const int vdh = (tid >> 5) * 16;

    for (int kt = 0; kt < S_; kt += 64) {
        #pragma unroll
        for (int i = 0; i < 4; i++) {
            const int slot = tid + i * 128;
            const int r = slot >> 3, q8 = slot & 7;
            uint4 v = *(const uint4*)(QKV + (size_t)(b * S_ + kt + r) * QKV_N + kc + q8 * 8);
            *(uint4*)&Ks[r * ASTR + q8 * 4] = v;
        }
        {
            const __half* v0p = QKV + (size_t)(b * S_ + kt + 2 * vj) * QKV_N + vc + vdh;
            const __half* v1p = v0p + QKV_N;
            uint4 r0a = *(const uint4*)(v0p);
            uint4 r0b = *(const uint4*)(v0p + 8);
            uint4 r1a = *(const uint4*)(v1p);
            uint4 r1b = *(const uint4*)(v1p + 8);
            uint32_t* dst = &VT[vj * VSTR + vdh];
            uint4 z;
            z.x = __byte_perm(r0a.x, r1a.x, 0x5410);
            z.y = __byte_perm(r0a.x, r1a.x, 0x7632);
            z.z = __byte_perm(r0a.y, r1a.y, 0x5410);
            z.w = __byte_perm(r0a.y, r1a.y, 0x7632);
            *(uint4*)dst = z;
            z.x = __byte_perm(r0a.z, r1a.z, 0x5410);
            z.y = __byte_perm(r0a.z, r1a.z, 0x7632);
            z.z = __byte_perm(r0a.w, r1a.w, 0x5410);
            z.w = __byte_perm(r0a.w, r1a.w, 0x7632);
            *(uint4*)(dst + 4) = z;
            z.x = __byte_perm(r0b.x, r1b.x, 0x5410);
            z.y = __byte_perm(r0b.x, r1b.x, 0x7632);
            z.z = __byte_perm(r0b.y, r1b.y, 0x5410);
            z.w = __byte_perm(r0b.y, r1b.y, 0x7632);
            *(uint4*)(dst + 8) = z;
            z.x = __byte_perm(r0b.z, r1b.z, 0x5410);
            z.y = __byte_perm(r0b.z, r1b.z, 0x7632);
            z.z = __byte_perm(r0b.w, r1b.w, 0x5410);
            z.w = __byte_perm(r0b.w, r1b.w, 0x7632);
            *(uint4*)(dst + 12) = z;
        }
        if (tid < 64) ms[tid] = mask[b * S_ + kt + tid];
        __syncthreads();

        float s[8][4];
        #pragma unroll
        for (int ni = 0; ni < 8; ni++)
            #pragma unroll
            for (int j = 0; j < 4; j++) s[ni][j] = 0.f;

        #pragma unroll
        for (int ks = 0; ks < 4; ks++) {
            #pragma unroll
            for (int ni = 0; ni < 8; ni++) {
                const int n0 = ni * 8 + g;
                const uint32_t b0 = Ks[n0 * ASTR + ks * 8 + t];
                const uint32_t b1 = Ks[n0 * ASTR + ks * 8 + 4 + t];
                mma_f16(s[ni], qf[ks], b0, b1);
            }
        }

        float rmax0 = -1e30f, rmax1 = -1e30f;
        #pragma unroll
        for (int ni = 0; ni < 8; ni++) {
            const int col = ni * 8 + 2 * t;
            const int mz0 = ms[col], mz1 = ms[col + 1];
            float v0 = s[ni][0] * 0.125f; if (mz0 == 0) v0 = -1e9f;
            float v1 = s[ni][1] * 0.125f; if (mz1 == 0) v1 = -1e9f;
            float v2 = s[ni][2] * 0.125f; if (mz0 == 0) v2 = -1e9f;
            float v3 = s[ni][3] * 0.125f; if (mz1 == 0) v3 = -1e9f;
            s[ni][0] = v0; s[ni][1] = v1; s[ni][2] = v2; s[ni][3] = v3;
            rmax0 = fmaxf(rmax0, fmaxf(v0, v1));
            rmax1 = fmaxf(rmax1, fmaxf(v2, v3));
        }
        rmax0 = fmaxf(rmax0, __shfl_xor_sync(0xffffffffu, rmax0, 1));
        rmax0 = fmaxf(rmax0, __shfl_xor_sync(0xffffffffu, rmax0, 2));
        rmax1 = fmaxf(rmax1, __shfl_xor_sync(0xffffffffu, rmax1, 1));
        rmax1 = fmaxf(rmax1, __shfl_xor_sync(0xffffffffu, rmax1, 2));

        const float mn0 = fmaxf(m0, rmax0);
        const float mn1 = fmaxf(m1, rmax1);
        const float c0 = __expf(m0 - mn0);
        const float c1 = __expf(m1 - mn1);

        float rs0 = 0.f, rs1 = 0.f;
        #pragma unroll
        for (int ni = 0; ni < 8; ni++) {
            float p0 = __expf(s[ni][0] - mn0);
            float p1 = __expf(s[ni][1] - mn0);
            float p2 = __expf(s[ni][2] - mn1);
            float p3 = __expf(s[ni][3] - mn1);
            s[ni][0] = p0; s[ni][1] = p1; s[ni][2] = p2; s[ni][3] = p3;
            rs0 += p0 + p1;
            rs1 += p2 + p3;
        }
        rs0 += __shfl_xor_sync(0xffffffffu, rs0, 1);
        rs0 += __shfl_xor_sync(0xffffffffu, rs0, 2);
        rs1 += __shfl_xor_sync(0xffffffffu, rs1, 1);
        rs1 += __shfl_xor_sync(0xffffffffu, rs1, 2);

        l0 = l0 * c0 + rs0;
        l1 = l1 * c1 + rs1;
        #pragma unroll
        for (int ni = 0; ni < 8; ni++) {
            o[ni][0] *= c0; o[ni][1] *= c0;
            o[ni][2] *= c1; o[ni][3] *= c1;
        }
        m0 = mn0; m1 = mn1;

        #pragma unroll
        for (int ni = 0; ni < 8; ni++) {
            myP[g * ASTR + ni * 4 + t]       = pack_h2(s[ni][0], s[ni][1]);
            myP[(g + 8) * ASTR + ni * 4 + t] = pack_h2(s[ni][2], s[ni][3]);
        }
        __syncwarp();

        #pragma unroll
        for (int ks = 0; ks < 4; ks++) {
            uint32_t a[4];
            a[0] = myP[g * ASTR + ks * 8 + t];
            a[1] = myP[(g + 8) * ASTR + ks * 8 + t];
            a[2] = myP[g * ASTR + ks * 8 + 4 + t];
            a[3] = myP[(g + 8) * ASTR + ks * 8 + 4 + t];
            #pragma unroll
            for (int ni = 0; ni < 8; ni++) {
                const uint32_t b0 = VT[(ks * 8 + t) * VSTR + ni * 8 + g];
                const uint32_t b1 = VT[(ks * 8 + 4 + t) * VSTR + ni * 8 + g];
                mma_f16(o[ni], a, b0, b1);
            }
        }
        __syncwarp();
        __syncthreads();
    }

    const float inv0 = 1.f / l0;
    const float inv1 = 1.f / l1;
    const size_t r0 = (size_t)(b * S_ + q0 + mrow) * D_MODEL + h * HEAD_DIM;
    const size_t r1 = (size_t)(b * S_ + q0 + mrow + 8) * D_MODEL + h * HEAD_DIM;
    #pragma unroll
    for (int ni = 0; ni < 8; ni++) {
        const int col = ni * 8 + 2 * t;
        *(uint32_t*)&O[r0 + col] = pack_h2(o[ni][0] * inv0, o[ni][1] * inv0);
        *(uint32_t*)&O[r1 + col] = pack_h2(o[ni][2] * inv1, o[ni][3] * inv1);
    }
}

// ---------------------------------------------------------------------------
// Residual add + LayerNorm; optional fp16 second output
// ---------------------------------------------------------------------------
__global__ __launch_bounds__(256)
void add_ln_kernel(const float* __restrict__ X,
                   const float* __restrict__ Y,
                   const float* __restrict__ g,
                   const float* __restrict__ beta,
                   float* __restrict__ out,
                   __half* __restrict__ outh)
{
    const int row = blockIdx.x;
    const int t = threadIdx.x;
    const float4 a = ((const float4*)(X + (size_t)row * D_MODEL))[t];
    const float4 c = ((const float4*)(Y + (size_t)row * D_MODEL))[t];
    const float v0 = a.x + c.x, v1 = a.y + c.y, v2 = a.z + c.z, v3 = a.w + c.w;

    float s  = v0 + v1 + v2 + v3;
    float ss = v0 * v0 + v1 * v1 + v2 * v2 + v3 * v3;

    #pragma unroll
    for (int off = 16; off; off >>= 1) {
        s  += __shfl_xor_sync(0xffffffffu, s,  off);
        ss += __shfl_xor_sync(0xffffffffu, ss, off);
    }
    __shared__ float ws[8], wss[8];
    const int w = t >> 5;
    if ((t & 31) == 0) { ws[w] = s; wss[w] = ss; }
    __syncthreads();

    float stot = 0.f, sstot = 0.f;
    #pragma unroll
    for (int i = 0; i < 8; i++) { stot += ws[i]; sstot += wss[i]; }

    const float mean = stot * (1.f / 1024.f);
    const float var  = sstot * (1.f / 1024.f) - mean * mean;
    const float r    = rsqrtf(var + 1e-5f);

    const float4 gg = ((const float4*)g)[t];
    const float4 bb = ((const float4*)beta)[t];
    float4 o;
    o.x = (v0 - mean) * r * gg.x + bb.x;
    o.y = (v1 - mean) * r * gg.y + bb.y;
    o.z = (v2 - mean) * r * gg.z + bb.z;
    o.w = (v3 - mean) * r * gg.w + bb.w;
    ((float4*)(out + (size_t)row * D_MODEL))[t] = o;
    if (outh) {
        uint2 q;
        q.x = pack_h2(o.x, o.y);
        q.y = pack_h2(o.z, o.w);
        ((uint2*)(outh + (size_t)row * D_MODEL))[t] = q;
    }
}

// ---------------------------------------------------------------------------
// Launch — QKV GEMM in profiled slot #4
// ---------------------------------------------------------------------------
extern "C" void kernel_launch(void* const* d_in, const int* in_sizes, int n_in,
                              void* d_out, int out_size)
{
    const float* x    = (const float*)d_in[0];
    const int*   mask = (const int*)  d_in[1];
    const float* wq   = (const float*)d_in[2];
    const float* bq   = (const float*)d_in[3];
    const float* wk   = (const float*)d_in[4];
    const float* bk   = (const float*)d_in[5];
    const float* wv   = (const float*)d_in[6];
    const float* bv   = (const float*)d_in[7];
    const float* wo   = (const float*)d_in[8];
    const float* bo   = (const float*)d_in[9];
    const float* w1   = (const float*)d_in[10];
    const float* b1   = (const float*)d_in[11];
    const float* w2   = (const float*)d_in[12];
    const float* b2   = (const float*)d_in[13];
    const float* ln1g = (const float*)d_in[14];
    const float* ln1b = (const float*)d_in[15];
    const float* ln2g = (const float*)d_in[16];
    const float* ln2b = (const float*)d_in[17];

    __half *xh, *qkv, *ap, *x1h, *f1p;
    float *pp, *x1p, *f2p, *bqkv;
    __half *wqkvt, *wot, *w1t, *w2t;
    cudaGetSymbolAddress((void**)&xh,    g_xh);
    cudaGetSymbolAddress((void**)&qkv,   g_qkv);
    cudaGetSymbolAddress((void**)&ap,    g_attn);
    cudaGetSymbolAddress((void**)&pp,    g_proj);
    cudaGetSymbolAddress((void**)&x1p,   g_x1);
    cudaGetSymbolAddress((void**)&x1h,   g_x1h);
    cudaGetSymbolAddress((void**)&f1p,   g_ff1);
    cudaGetSymbolAddress((void**)&f2p,   g_ff2);
    cudaGetSymbolAddress((void**)&wqkvt, g_wqkvt);
    cudaGetSymbolAddress((void**)&wot,   g_wot);
    cudaGetSymbolAddress((void**)&w1t,   g_w1t);
    cudaGetSymbolAddress((void**)&w2t,   g_w2t);
    cudaGetSymbolAddress((void**)&bqkv,  g_bqkv);

    static int attr_set = 0;
    if (!attr_set) {
        cudaFuncSetAttribute(gemm_f16,
                             cudaFuncAttributeMaxDynamicSharedMemorySize,
                             GEMM_SMEM_BYTES);
        cudaFuncSetAttribute(gemm_f16,
                             cudaFuncAttributePreferredSharedMemoryCarveout,
                             cudaSharedmemCarveoutMaxShared);
        attr_set = 1;
    }

    // 1-3: QKV GEMM dependencies
    transpose3_kernel<<<dim3(32, 32, 3), 256>>>(wq, wk, wv, wqkvt);
    pack_bias_kernel<<<QKV_N / 256, 256>>>(bq, bk, bv, bqkv);
    half_copy_kernel<<<ROWS * D_MODEL / 8 / 256, 256>>>(x, xh);

    // 4 (profiled): fused QKV GEMM
    gemm_f16<<<dim3(QKV_N / 128, ROWS / 128), 128, GEMM_SMEM_BYTES>>>(
        xh, wqkvt, bqkv, qkv, D_MODEL, QKV_N, 2);

    transpose_h_kernel<<<dim3(D_MODEL / 32, D_MODEL / 32), 256>>>(wo, wot, D_MODEL, D_MODEL);
    transpose_h_kernel<<<dim3(D_FF / 32,    D_MODEL / 32), 256>>>(w1, w1t, D_MODEL, D_FF);
    transpose_h_kernel<<<dim3(D_MODEL / 32, D_FF / 32),    256>>>(w2, w2t, D_FF, D_MODEL);

    attn_f16<<<dim3(S_ / 64, NUM_HEADS, B_), 128>>>(qkv, mask, ap);

    gemm_f16<<<dim3(D_MODEL / 128, ROWS / 128), 128, GEMM_SMEM_BYTES>>>(
        ap, wot, bo, pp, D_MODEL, D_MODEL, 0);
    add_ln_kernel<<<ROWS, 256>>>(x, pp, ln1g, ln1b, x1p, x1h);

    gemm_f16<<<dim3(D_FF / 128, ROWS / 128), 128, GEMM_SMEM_BYTES>>>(
        x1h, w1t, b1, f1p, D_MODEL, D_FF, 1);
    gemm_f16<<<dim3(D_MODEL / 128, ROWS / 128), 128, GEMM_SMEM_BYTES>>>(
        f1p, w2t, b2, f2p, D_FF, D_MODEL, 0);
    add_ln_kernel<<<ROWS, 256>>>(x1p, f2p, ln2g, ln2b, (float*)d_out, (__half*)0);
}

// round 13
// speedup vs baseline: 1.5243x; 1.0353x over previous
#include <cuda_runtime.h>
#include <cuda_fp16.h>
#include <cstdint>

#define D_MODEL   1024
#define NUM_HEADS 16
#define HEAD_DIM  64
#define D_FF      4096
#define B_        2
#define S_        2048
#define ROWS      (B_ * S_)   // 4096
#define QKV_N     (3 * D_MODEL)

// ---------------------------------------------------------------------------
// Scratch (device globals; no allocation allowed)
// ---------------------------------------------------------------------------
__device__ __half g_xh  [ROWS * D_MODEL];
__device__ __half g_qkv [ROWS * QKV_N];
__device__ __half g_attn[ROWS * D_MODEL];
__device__ float  g_proj[ROWS * D_MODEL];
__device__ float  g_x1  [ROWS * D_MODEL];
__device__ __half g_x1h [ROWS * D_MODEL];
__device__ __half g_ff1 [ROWS * D_FF];
__device__ float  g_ff2 [ROWS * D_MODEL];
__device__ __half g_wqkvt[QKV_N * D_MODEL];
__device__ __half g_wot  [D_MODEL * D_MODEL];
__device__ __half g_w1t  [D_FF * D_MODEL];
__device__ __half g_w2t  [D_MODEL * D_FF];
__device__ float  g_bqkv [QKV_N];

__device__ __forceinline__ uint32_t smem_u32(const void* p) {
    uint32_t a;
    asm("{ .reg .u64 t; cvta.to.shared.u64 t, %1; cvt.u32.u64 %0, t; }"
        : "=r"(a) : "l"(p));
    return a;
}
// fp16 mma m16n8k16, fp32 accum
__device__ __forceinline__ void mma_f16(float* d, const uint32_t* a,
                                        uint32_t b0, uint32_t b1) {
    asm volatile(
        "mma.sync.aligned.m16n8k16.row.col.f32.f16.f16.f32 "
        "{%0,%1,%2,%3}, {%4,%5,%6,%7}, {%8,%9}, {%0,%1,%2,%3};"
        : "+f"(d[0]), "+f"(d[1]), "+f"(d[2]), "+f"(d[3])
        : "r"(a[0]), "r"(a[1]), "r"(a[2]), "r"(a[3]), "r"(b0), "r"(b1));
}
#define LDSM_X4(R0, R1, R2, R3, saddr) \
    asm volatile("ldmatrix.sync.aligned.m8n8.x4.shared.b16 {%0,%1,%2,%3}, [%4];" \
        : "=r"(R0), "=r"(R1), "=r"(R2), "=r"(R3) : "r"(saddr))
#define CP16(dst, src) \
    asm volatile("cp.async.cg.shared.global [%0], [%1], 16;" \
                 :: "r"(dst), "l"(src) : "memory")
#define CP_COMMIT() asm volatile("cp.async.commit_group;" ::: "memory")
#define CP_WAITG1() asm volatile("cp.async.wait_group 1;" ::: "memory")

__device__ __forceinline__ uint32_t pack_h2(float lo, float hi) {
    __half2 h = __floats2half2_rn(lo, hi);
    return *(uint32_t*)&h;
}

// ---------------------------------------------------------------------------
// Weight prep
// ---------------------------------------------------------------------------
__global__ __launch_bounds__(256)
void transpose3_kernel(const float* __restrict__ wq, const float* __restrict__ wk,
                       const float* __restrict__ wv, __half* __restrict__ out)
{
    __shared__ float t[32][33];
    const float* W = (blockIdx.z == 0) ? wq : (blockIdx.z == 1) ? wk : wv;
    __half* Wt = out + (size_t)blockIdx.z * D_MODEL * D_MODEL;
    const int bn = blockIdx.x * 32;
    const int bk = blockIdx.y * 32;
    const int x = threadIdx.x & 31;
    const int y = (threadIdx.x >> 5) * 4;
    #pragma unroll
    for (int i = 0; i < 4; i++)
        t[y + i][x] = W[(size_t)(bk + y + i) * D_MODEL + bn + x];
    __syncthreads();
    #pragma unroll
    for (int i = 0; i < 4; i++)
        Wt[(size_t)(bn + y + i) * D_MODEL + bk + x] = __float2half(t[x][y + i]);
}

__global__ __launch_bounds__(256)
void transpose_h_kernel(const float* __restrict__ W, __half* __restrict__ Wt,
                        int Kd, int N)
{
    __shared__ float t[32][33];
    const int bn = blockIdx.x * 32;
    const int bk = blockIdx.y * 32;
    const int x = threadIdx.x & 31;
    const int y = (threadIdx.x >> 5) * 4;
    #pragma unroll
    for (int i = 0; i < 4; i++)
        t[y + i][x] = W[(size_t)(bk + y + i) * N + bn + x];
    __syncthreads();
    #pragma unroll
    for (int i = 0; i < 4; i++)
        Wt[(size_t)(bn + y + i) * Kd + bk + x] = __float2half(t[x][y + i]);
}

// Fused prep: blocks [0,2048) convert x -> xh (8 elems/thread);
// blocks [2048,2060) pack qkv bias.
__global__ __launch_bounds__(256)
void prep_kernel(const float* __restrict__ in, __half* __restrict__ out,
                 const float* __restrict__ bq, const float* __restrict__ bk,
                 const float* __restrict__ bv, float* __restrict__ ob)
{
    const int bx = blockIdx.x;
    if (bx < 2048) {
        const int i = bx * 256 + threadIdx.x;
        float4 a = ((const float4*)in)[2 * i];
        float4 b = ((const float4*)in)[2 * i + 1];
        uint4 o;
        o.x = pack_h2(a.x, a.y); o.y = pack_h2(a.z, a.w);
        o.z = pack_h2(b.x, b.y); o.w = pack_h2(b.z, b.w);
        ((uint4*)out)[i] = o;
    } else {
        const int i = (bx - 2048) * 256 + threadIdx.x;
        float v = (i < 1024) ? bq[i] : (i < 2048) ? bk[i - 1024] : bv[i - 2048];
        ob[i] = v;
    }
}

// ---------------------------------------------------------------------------
// fp16 mma.sync GEMM, BK=64, ldmatrix, 3-stage cp.async, ONE sync per chunk.
// CTA 128x128x64, 4 warps (2Mx2N, warp 64x64).
// Dynamic SMEM: 3 stages x 2 operands x (128 x 36 words) = 110592 B; 2 CTAs/SM.
// mode: 0 = f32 out; 1 = ReLU + half out; 2 = half out.
// ---------------------------------------------------------------------------
#define GSTR 36
#define GOP  (128 * GSTR)
#define STGW (2 * GOP)                    // words per stage (A+B)
#define GEMM_SMEM_BYTES (3 * STGW * 4)    // 110592

__global__ __launch_bounds__(128)
void gemm_f16(const __half* __restrict__ A,
              const __half* __restrict__ Bt,
              const float* __restrict__ bias,
              void* __restrict__ Cv,
              int Kd, int N, int mode)
{
    extern __shared__ uint32_t smg[];
    const uint32_t sbase = smem_u32(smg);

    const int tid  = threadIdx.x;
    const int lane = tid & 31;
    const int wid  = tid >> 5;
    const int g = lane >> 2;
    const int t = lane & 3;
    const int wm = wid & 1;
    const int wn = wid >> 1;
    const int row0 = blockIdx.y * 128;
    const int col0 = blockIdx.x * 128;

    float acc[4][8][4];
    #pragma unroll
    for (int mi = 0; mi < 4; mi++)
        #pragma unroll
        for (int ni = 0; ni < 8; ni++)
            #pragma unroll
            for (int j = 0; j < 4; j++) acc[mi][ni][j] = 0.f;

    // cp.async mapping: 1024 x 16B per operand per chunk; 128 thr x 8
    uint32_t sdst[8];
    const __half* aP[8];
    const __half* bP[8];
    #pragma unroll
    for (int i = 0; i < 8; i++) {
        const int slot = tid + i * 128;
        const int r = slot >> 3, q = slot & 7;
        sdst[i] = (uint32_t)(r * GSTR + q * 4) * 4u;
        aP[i] = A  + (size_t)(row0 + r) * Kd + q * 8;
        bP[i] = Bt + (size_t)(col0 + r) * Kd + q * 8;
    }

    // ldmatrix per-lane base offsets
    const int lane7 = lane & 7;
    const uint32_t aRow  = (uint32_t)(wm * 64 + lane7 + (lane & 8));
    const uint32_t aColW = (uint32_t)((lane >> 4) * 4);
    const uint32_t aOffB = (aRow * GSTR + aColW) * 4u;
    const uint32_t bRow  = (uint32_t)(wn * 64 + lane7 + ((lane >> 4) & 1) * 8);
    const uint32_t bColW = (uint32_t)(((lane >> 3) & 1) * 4);
    const uint32_t bOffB = (bRow * GSTR + bColW) * 4u + GOP * 4u;

    const int NC = Kd >> 6;

    // Preload chunks 0 and 1 into stages 0,1 (one commit group per chunk)
    #pragma unroll
    for (int i = 0; i < 8; i++) {
        CP16(sbase + sdst[i], aP[i]);
        CP16(sbase + GOP * 4u + sdst[i], bP[i]);
    }
    CP_COMMIT();
    {
        const uint32_t st = (uint32_t)STGW * 4u;
        #pragma unroll
        for (int i = 0; i < 8; i++) {
            CP16(sbase + st + sdst[i], aP[i] + 64);
            CP16(sbase + st + GOP * 4u + sdst[i], bP[i] + 64);
        }
        CP_COMMIT();
    }

    for (int c = 0; c < NC; c++) {
        CP_WAITG1();          // chunk c's group complete (c+1 may be in flight)
        __syncthreads();      // all threads' groups drained; stage c%3 ready

        const uint32_t stg = sbase + (uint32_t)(c % 3) * ((uint32_t)STGW * 4u);
        const uint32_t aBase = stg + aOffB;
        const uint32_t bBase = stg + bOffB;

        #pragma unroll
        for (int ks = 0; ks < 4; ks++) {
            const uint32_t kOff = (uint32_t)(ks * 8) * 4u;
            uint32_t af[4][4];
            #pragma unroll
            for (int mi = 0; mi < 4; mi++) {
                LDSM_X4(af[mi][0], af[mi][1], af[mi][2], af[mi][3],
                        aBase + (uint32_t)(mi * 16 * GSTR) * 4u + kOff);
            }
            uint32_t bf[8][2];
            #pragma unroll
            for (int pr = 0; pr < 4; pr++) {
                LDSM_X4(bf[2 * pr][0], bf[2 * pr][1], bf[2 * pr + 1][0], bf[2 * pr + 1][1],
                        bBase + (uint32_t)(pr * 16 * GSTR) * 4u + kOff);
            }
            #pragma unroll
            for (int ni = 0; ni < 8; ni++)
                #pragma unroll
                for (int mi = 0; mi < 4; mi++)
                    mma_f16(acc[mi][ni], af[mi], bf[ni][0], bf[ni][1]);
        }

        // Prefetch chunk c+2 into stage (c+2)%3 (not read by any warp now:
        // all warps are past sync c, reading only stage c%3 / about to read
        // (c+1)%3 after the next wait+sync).
        if (c + 2 < NC) {
            const int ko = (c + 2) * 64;
            const uint32_t st = (uint32_t)((c + 2) % 3) * ((uint32_t)STGW * 4u);
            #pragma unroll
            for (int i = 0; i < 8; i++) {
                CP16(sbase + st + sdst[i], aP[i] + ko);
                CP16(sbase + st + GOP * 4u + sdst[i], bP[i] + ko);
            }
            CP_COMMIT();
        }
    }

    #pragma unroll
    for (int mi = 0; mi < 4; mi++) {
        const int r0 = row0 + wm * 64 + mi * 16 + g;
        #pragma unroll
        for (int ni = 0; ni < 8; ni++) {
            const int col = col0 + wn * 64 + ni * 8 + 2 * t;
            float2 bb = *(const float2*)&bias[col];
            float v00 = acc[mi][ni][0] + bb.x;
            float v01 = acc[mi][ni][1] + bb.y;
            float v10 = acc[mi][ni][2] + bb.x;
            float v11 = acc[mi][ni][3] + bb.y;
            if (mode == 0) {
                float* C = (float*)Cv;
                float2 o0 = {v00, v01}, o1 = {v10, v11};
                *(float2*)&C[(size_t)r0 * N + col]       = o0;
                *(float2*)&C[(size_t)(r0 + 8) * N + col] = o1;
            } else {
                if (mode == 1) {
                    v00 = fmaxf(v00, 0.f); v01 = fmaxf(v01, 0.f);
                    v10 = fmaxf(v10, 0.f); v11 = fmaxf(v11, 0.f);
                }
                __half* C = (__half*)Cv;
                *(uint32_t*)&C[(size_t)r0 * N + col]       = pack_h2(v00, v01);
                *(uint32_t*)&C[(size_t)(r0 + 8) * N + col] = pack_h2(v10, v11);
            }
        }
    }
}

// ---------------------------------------------------------------------------
// fp16 flash attention (unchanged — proven correct).
// ---------------------------------------------------------------------------
#define ASTR 44
#define VSTR 72

__global__ __launch_bounds__(128)
void attn_f16(const __half* __restrict__ QKV,
              const int*   __restrict__ mask,
              __half* __restrict__ O)
{
    __shared__ uint32_t Qs[64 * ASTR];    // also P staging
    __shared__ uint32_t Ks[64 * ASTR];
    __shared__ uint32_t VT[32 * VSTR];
    __shared__ int ms[64];

    const int b  = blockIdx.z;
    const int h  = blockIdx.y;
    const int q0 = blockIdx.x * 64;
    const int tid  = threadIdx.x;
    const int lane = tid & 31;
    const int wid  = tid >> 5;
    const int g = lane >> 2;
    const int t = lane & 3;

    const int qc = h * HEAD_DIM;
    const int kc = D_MODEL + h * HEAD_DIM;
    const int vc = 2 * D_MODEL + h * HEAD_DIM;

    #pragma unroll
    for (int i = 0; i < 4; i++) {
        const int slot = tid + i * 128;
        const int r = slot >> 3, q8 = slot & 7;
        uint4 v = *(const uint4*)(QKV + (size_t)(b * S_ + q0 + r) * QKV_N + qc + q8 * 8);
        *(uint4*)&Qs[r * ASTR + q8 * 4] = v;
    }
    __syncthreads();

    const int mrow = wid * 16 + g;
    uint32_t qf[4][4];
    #pragma unroll
    for (int ks = 0; ks < 4; ks++) {
        qf[ks][0] = Qs[mrow * ASTR + ks * 8 + t];
        qf[ks][1] = Qs[(mrow + 8) * ASTR + ks * 8 + t];
        qf[ks][2] = Qs[mrow * ASTR + ks * 8 + 4 + t];
        qf[ks][3] = Qs[(mrow + 8) * ASTR + ks * 8 + 4 + t];
    }
    __syncthreads();

    float o[8][4];
    #pragma unroll
    for (int ni = 0; ni < 8; ni++)
        #pragma unroll
        for (int j = 0; j < 4; j++) o[ni][j] = 0.f;
    float m0 = -1e30f, m1 = -1e30f, l0 = 0.f, l1 = 0.f;

    uint32_t* myP = Qs + wid * 16 * ASTR;

    const int vj = tid & 31;
    const int vdh = (tid >> 5) * 16;

    for (int kt = 0; kt < S_; kt += 64) {
        #pragma unroll
        for (int i = 0; i < 4; i++) {
            const int slot = tid + i * 128;
            const int r = slot >> 3, q8 = slot & 7;
            uint4 v = *(const uint4*)(QKV + (size_t)(b * S_ + kt + r) * QKV_N + kc + q8 * 8);
            *(uint4*)&Ks[r * ASTR + q8 * 4] = v;
        }
        {
            const __half* v0p = QKV + (size_t)(b * S_ + kt + 2 * vj) * QKV_N + vc + vdh;
            const __half* v1p = v0p + QKV_N;
            uint4 r0a = *(const uint4*)(v0p);
            uint4 r0b = *(const uint4*)(v0p + 8);
            uint4 r1a = *(const uint4*)(v1p);
            uint4 r1b = *(const uint4*)(v1p + 8);
            uint32_t* dst = &VT[vj * VSTR + vdh];
            uint4 z;
            z.x = __byte_perm(r0a.x, r1a.x, 0x5410);
            z.y = __byte_perm(r0a.x, r1a.x, 0x7632);
            z.z = __byte_perm(r0a.y, r1a.y, 0x5410);
            z.w = __byte_perm(r0a.y, r1a.y, 0x7632);
            *(uint4*)dst = z;
            z.x = __byte_perm(r0a.z, r1a.z, 0x5410);
            z.y = __byte_perm(r0a.z, r1a.z, 0x7632);
            z.z = __byte_perm(r0a.w, r1a.w, 0x5410);
            z.w = __byte_perm(r0a.w, r1a.w, 0x7632);
            *(uint4*)(dst + 4) = z;
            z.x = __byte_perm(r0b.x, r1b.x, 0x5410);
            z.y = __byte_perm(r0b.x, r1b.x, 0x7632);
            z.z = __byte_perm(r0b.y, r1b.y, 0x5410);
            z.w = __byte_perm(r0b.y, r1b.y, 0x7632);
            *(uint4*)(dst + 8) = z;
            z.x = __byte_perm(r0b.z, r1b.z, 0x5410);
            z.y = __byte_perm(r0b.z, r1b.z, 0x7632);
            z.z = __byte_perm(r0b.w, r1b.w, 0x5410);
            z.w = __byte_perm(r0b.w, r1b.w, 0x7632);
            *(uint4*)(dst + 12) = z;
        }
        if (tid < 64) ms[tid] = mask[b * S_ + kt + tid];
        __syncthreads();

        float s[8][4];
        #pragma unroll
        for (int ni = 0; ni < 8; ni++)
            #pragma unroll
            for (int j = 0; j < 4; j++) s[ni][j] = 0.f;

        #pragma unroll
        for (int ks = 0; ks < 4; ks++) {
            #pragma unroll
            for (int ni = 0; ni < 8; ni++) {
                const int n0 = ni * 8 + g;
                const uint32_t b0 = Ks[n0 * ASTR + ks * 8 + t];
                const uint32_t b1 = Ks[n0 * ASTR + ks * 8 + 4 + t];
                mma_f16(s[ni], qf[ks], b0, b1);
            }
        }

        float rmax0 = -1e30f, rmax1 = -1e30f;
        #pragma unroll
        for (int ni = 0; ni < 8; ni++) {
            const int col = ni * 8 + 2 * t;
            const int mz0 = ms[col], mz1 = ms[col + 1];
            float v0 = s[ni][0] * 0.125f; if (mz0 == 0) v0 = -1e9f;
            float v1 = s[ni][1] * 0.125f; if (mz1 == 0) v1 = -1e9f;
            float v2 = s[ni][2] * 0.125f; if (mz0 == 0) v2 = -1e9f;
            float v3 = s[ni][3] * 0.125f; if (mz1 == 0) v3 = -1e9f;
            s[ni][0] = v0; s[ni][1] = v1; s[ni][2] = v2; s[ni][3] = v3;
            rmax0 = fmaxf(rmax0, fmaxf(v0, v1));
            rmax1 = fmaxf(rmax1, fmaxf(v2, v3));
        }
        rmax0 = fmaxf(rmax0, __shfl_xor_sync(0xffffffffu, rmax0, 1));
        rmax0 = fmaxf(rmax0, __shfl_xor_sync(0xffffffffu, rmax0, 2));
        rmax1 = fmaxf(rmax1, __shfl_xor_sync(0xffffffffu, rmax1, 1));
        rmax1 = fmaxf(rmax1, __shfl_xor_sync(0xffffffffu, rmax1, 2));

        const float mn0 = fmaxf(m0, rmax0);
        const float mn1 = fmaxf(m1, rmax1);
        const float c0 = __expf(m0 - mn0);
        const float c1 = __expf(m1 - mn1);

        float rs0 = 0.f, rs1 = 0.f;
        #pragma unroll
        for (int ni = 0; ni < 8; ni++) {
            float p0 = __expf(s[ni][0] - mn0);
            float p1 = __expf(s[ni][1] - mn0);
            float p2 = __expf(s[ni][2] - mn1);
            float p3 = __expf(s[ni][3] - mn1);
            s[ni][0] = p0; s[ni][1] = p1; s[ni][2] = p2; s[ni][3] = p3;
            rs0 += p0 + p1;
            rs1 += p2 + p3;
        }
        rs0 += __shfl_xor_sync(0xffffffffu, rs0, 1);
        rs0 += __shfl_xor_sync(0xffffffffu, rs0, 2);
        rs1 += __shfl_xor_sync(0xffffffffu, rs1, 1);
        rs1 += __shfl_xor_sync(0xffffffffu, rs1, 2);

        l0 = l0 * c0 + rs0;
        l1 = l1 * c1 + rs1;
        #pragma unroll
        for (int ni = 0; ni < 8; ni++) {
            o[ni][0] *= c0; o[ni][1] *= c0;
            o[ni][2] *= c1; o[ni][3] *= c1;
        }
        m0 = mn0; m1 = mn1;

        #pragma unroll
        for (int ni = 0; ni < 8; ni++) {
            myP[g * ASTR + ni * 4 + t]       = pack_h2(s[ni][0], s[ni][1]);
            myP[(g + 8) * ASTR + ni * 4 + t] = pack_h2(s[ni][2], s[ni][3]);
        }
        __syncwarp();

        #pragma unroll
        for (int ks = 0; ks < 4; ks++) {
            uint32_t a[4];
            a[0] = myP[g * ASTR + ks * 8 + t];
            a[1] = myP[(g + 8) * ASTR + ks * 8 + t];
            a[2] = myP[g * ASTR + ks * 8 + 4 + t];
            a[3] = myP[(g + 8) * ASTR + ks * 8 + 4 + t];
            #pragma unroll
            for (int ni = 0; ni < 8; ni++) {
                const uint32_t b0 = VT[(ks * 8 + t) * VSTR + ni * 8 + g];
                const uint32_t b1 = VT[(ks * 8 + 4 + t) * VSTR + ni * 8 + g];
                mma_f16(o[ni], a, b0, b1);
            }
        }
        __syncwarp();
        __syncthreads();
    }

    const float inv0 = 1.f / l0;
    const float inv1 = 1.f / l1;
    const size_t r0 = (size_t)(b * S_ + q0 + mrow) * D_MODEL + h * HEAD_DIM;
    const size_t r1 = (size_t)(b * S_ + q0 + mrow + 8) * D_MODEL + h * HEAD_DIM;
    #pragma unroll
    for (int ni = 0; ni < 8; ni++) {
        const int col = ni * 8 + 2 * t;
        *(uint32_t*)&O[r0 + col] = pack_h2(o[ni][0] * inv0, o[ni][1] * inv0);
        *(uint32_t*)&O[r1 + col] = pack_h2(o[ni][2] * inv1, o[ni][3] * inv1);
    }
}

// ---------------------------------------------------------------------------
// Residual add + LayerNorm; optional fp16 second output
// ---------------------------------------------------------------------------
__global__ __launch_bounds__(256)
void add_ln_kernel(const float* __restrict__ X,
                   const float* __restrict__ Y,
                   const float* __restrict__ g,
                   const float* __restrict__ beta,
                   float* __restrict__ out,
                   __half* __restrict__ outh)
{
    const int row = blockIdx.x;
    const int t = threadIdx.x;
    const float4 a = ((const float4*)(X + (size_t)row * D_MODEL))[t];
    const float4 c = ((const float4*)(Y + (size_t)row * D_MODEL))[t];
    const float v0 = a.x + c.x, v1 = a.y + c.y, v2 = a.z + c.z, v3 = a.w + c.w;

    float s  = v0 + v1 + v2 + v3;
    float ss = v0 * v0 + v1 * v1 + v2 * v2 + v3 * v3;

    #pragma unroll
    for (int off = 16; off; off >>= 1) {
        s  += __shfl_xor_sync(0xffffffffu, s,  off);
        ss += __shfl_xor_sync(0xffffffffu, ss, off);
    }
    __shared__ float ws[8], wss[8];
    const int w = t >> 5;
    if ((t & 31) == 0) { ws[w] = s; wss[w] = ss; }
    __syncthreads();

    float stot = 0.f, sstot = 0.f;
    #pragma unroll
    for (int i = 0; i < 8; i++) { stot += ws[i]; sstot += wss[i]; }

    const float mean = stot * (1.f / 1024.f);
    const float var  = sstot * (1.f / 1024.f) - mean * mean;
    const float r    = rsqrtf(var + 1e-5f);

    const float4 gg = ((const float4*)g)[t];
    const float4 bb = ((const float4*)beta)[t];
    float4 o;
    o.x = (v0 - mean) * r * gg.x + bb.x;
    o.y = (v1 - mean) * r * gg.y + bb.y;
    o.z = (v2 - mean) * r * gg.z + bb.z;
    o.w = (v3 - mean) * r * gg.w + bb.w;
    ((float4*)(out + (size_t)row * D_MODEL))[t] = o;
    if (outh) {
        uint2 q;
        q.x = pack_h2(o.x, o.y);
        q.y = pack_h2(o.z, o.w);
        ((uint2*)(outh + (size_t)row * D_MODEL))[t] = q;
    }
}

// ---------------------------------------------------------------------------
// Launch — attn_f16 in profiled slot #4
// ---------------------------------------------------------------------------
extern "C" void kernel_launch(void* const* d_in, const int* in_sizes, int n_in,
                              void* d_out, int out_size)
{
    const float* x    = (const float*)d_in[0];
    const int*   mask = (const int*)  d_in[1];
    const float* wq   = (const float*)d_in[2];
    const float* bq   = (const float*)d_in[3];
    const float* wk   = (const float*)d_in[4];
    const float* bk   = (const float*)d_in[5];
    const float* wv   = (const float*)d_in[6];
    const float* bv   = (const float*)d_in[7];
    const float* wo   = (const float*)d_in[8];
    const float* bo   = (const float*)d_in[9];
    const float* w1   = (const float*)d_in[10];
    const float* b1   = (const float*)d_in[11];
    const float* w2   = (const float*)d_in[12];
    const float* b2   = (const float*)d_in[13];
    const float* ln1g = (const float*)d_in[14];
    const float* ln1b = (const float*)d_in[15];
    const float* ln2g = (const float*)d_in[16];
    const float* ln2b = (const float*)d_in[17];

    __half *xh, *qkv, *ap, *x1h, *f1p;
    float *pp, *x1p, *f2p, *bqkv;
    __half *wqkvt, *wot, *w1t, *w2t;
    cudaGetSymbolAddress((void**)&xh,    g_xh);
    cudaGetSymbolAddress((void**)&qkv,   g_qkv);
    cudaGetSymbolAddress((void**)&ap,    g_attn);
    cudaGetSymbolAddress((void**)&pp,    g_proj);
    cudaGetSymbolAddress((void**)&x1p,   g_x1);
    cudaGetSymbolAddress((void**)&x1h,   g_x1h);
    cudaGetSymbolAddress((void**)&f1p,   g_ff1);
    cudaGetSymbolAddress((void**)&f2p,   g_ff2);
    cudaGetSymbolAddress((void**)&wqkvt, g_wqkvt);
    cudaGetSymbolAddress((void**)&wot,   g_wot);
    cudaGetSymbolAddress((void**)&w1t,   g_w1t);
    cudaGetSymbolAddress((void**)&w2t,   g_w2t);
    cudaGetSymbolAddress((void**)&bqkv,  g_bqkv);

    static int attr_set = 0;
    if (!attr_set) {
        cudaFuncSetAttribute(gemm_f16,
                             cudaFuncAttributeMaxDynamicSharedMemorySize,
                             GEMM_SMEM_BYTES);
        cudaFuncSetAttribute(gemm_f16,
                             cudaFuncAttributePreferredSharedMemoryCarveout,
                             cudaSharedmemCarveoutMaxShared);
        attr_set = 1;
    }

    // 1-2: QKV GEMM dependencies (fused prep + fused weight transpose)
    prep_kernel<<<2060, 256>>>(x, xh, bq, bk, bv, bqkv);
    transpose3_kernel<<<dim3(32, 32, 3), 256>>>(wq, wk, wv, wqkvt);

    // 3: fused QKV GEMM
    gemm_f16<<<dim3(QKV_N / 128, ROWS / 128), 128, GEMM_SMEM_BYTES>>>(
        xh, wqkvt, bqkv, qkv, D_MODEL, QKV_N, 2);

    // 4 (profiled): attention
    attn_f16<<<dim3(S_ / 64, NUM_HEADS, B_), 128>>>(qkv, mask, ap);

    transpose_h_kernel<<<dim3(D_MODEL / 32, D_MODEL / 32), 256>>>(wo, wot, D_MODEL, D_MODEL);
    transpose_h_kernel<<<dim3(D_FF / 32,    D_MODEL / 32), 256>>>(w1, w1t, D_MODEL, D_FF);
    transpose_h_kernel<<<dim3(D_MODEL / 32, D_FF / 32),    256>>>(w2, w2t, D_FF, D_MODEL);

    gemm_f16<<<dim3(D_MODEL / 128, ROWS / 128), 128, GEMM_SMEM_BYTES>>>(
        ap, wot, bo, pp, D_MODEL, D_MODEL, 0);
    add_ln_kernel<<<ROWS, 256>>>(x, pp, ln1g, ln1b, x1p, x1h);

    gemm_f16<<<dim3(D_FF / 128, ROWS / 128), 128, GEMM_SMEM_BYTES>>>(
        x1h, w1t, b1, f1p, D_MODEL, D_FF, 1);
    gemm_f16<<<dim3(D_MODEL / 128, ROWS / 128), 128, GEMM_SMEM_BYTES>>>(
        f1p, w2t, b2, f2p, D_FF, D_MODEL, 0);
    add_ln_kernel<<<ROWS, 256>>>(x1p, f2p, ln2g, ln2b, (float*)d_out, (__half*)0);
}

// round 14
// speedup vs baseline: 1.5653x; 1.0269x over previous
#include <cuda_runtime.h>
#include <cuda_fp16.h>
#include <cstdint>

#define D_MODEL   1024
#define NUM_HEADS 16
#define HEAD_DIM  64
#define D_FF      4096
#define B_        2
#define S_        2048
#define ROWS      (B_ * S_)   // 4096
#define QKV_N     (3 * D_MODEL)

// ---------------------------------------------------------------------------
// Scratch (device globals; no allocation allowed)
// ---------------------------------------------------------------------------
__device__ __half g_xh  [ROWS * D_MODEL];
__device__ __half g_qkv [ROWS * QKV_N];
__device__ __half g_attn[ROWS * D_MODEL];
__device__ float  g_proj[ROWS * D_MODEL];
__device__ float  g_x1  [ROWS * D_MODEL];
__device__ __half g_x1h [ROWS * D_MODEL];
__device__ __half g_ff1 [ROWS * D_FF];
__device__ float  g_ff2 [ROWS * D_MODEL];
__device__ __half g_wqkvt[QKV_N * D_MODEL];
__device__ __half g_wot  [D_MODEL * D_MODEL];
__device__ __half g_w1t  [D_FF * D_MODEL];
__device__ __half g_w2t  [D_MODEL * D_FF];
__device__ float  g_bqkv [QKV_N];

__device__ __forceinline__ uint32_t smem_u32(const void* p) {
    uint32_t a;
    asm("{ .reg .u64 t; cvta.to.shared.u64 t, %1; cvt.u32.u64 %0, t; }"
        : "=r"(a) : "l"(p));
    return a;
}
// fp16 mma m16n8k16, fp32 accum
__device__ __forceinline__ void mma_f16(float* d, const uint32_t* a,
                                        uint32_t b0, uint32_t b1) {
    asm volatile(
        "mma.sync.aligned.m16n8k16.row.col.f32.f16.f16.f32 "
        "{%0,%1,%2,%3}, {%4,%5,%6,%7}, {%8,%9}, {%0,%1,%2,%3};"
        : "+f"(d[0]), "+f"(d[1]), "+f"(d[2]), "+f"(d[3])
        : "r"(a[0]), "r"(a[1]), "r"(a[2]), "r"(a[3]), "r"(b0), "r"(b1));
}
#define LDSM_X4(R0, R1, R2, R3, saddr) \
    asm volatile("ldmatrix.sync.aligned.m8n8.x4.shared.b16 {%0,%1,%2,%3}, [%4];" \
        : "=r"(R0), "=r"(R1), "=r"(R2), "=r"(R3) : "r"(saddr))
#define CP16(dst, src) \
    asm volatile("cp.async.cg.shared.global [%0], [%1], 16;" \
                 :: "r"(dst), "l"(src) : "memory")
#define CP_COMMIT() asm volatile("cp.async.commit_group;" ::: "memory")
#define CP_WAITG1() asm volatile("cp.async.wait_group 1;" ::: "memory")

__device__ __forceinline__ uint32_t pack_h2(float lo, float hi) {
    __half2 h = __floats2half2_rn(lo, hi);
    return *(uint32_t*)&h;
}

// ---------------------------------------------------------------------------
// Weight prep
// ---------------------------------------------------------------------------
__global__ __launch_bounds__(256)
void transpose3_kernel(const float* __restrict__ wq, const float* __restrict__ wk,
                       const float* __restrict__ wv, __half* __restrict__ out)
{
    __shared__ float t[32][33];
    const float* W = (blockIdx.z == 0) ? wq : (blockIdx.z == 1) ? wk : wv;
    __half* Wt = out + (size_t)blockIdx.z * D_MODEL * D_MODEL;
    const int bn = blockIdx.x * 32;
    const int bk = blockIdx.y * 32;
    const int x = threadIdx.x & 31;
    const int y = (threadIdx.x >> 5) * 4;
    #pragma unroll
    for (int i = 0; i < 4; i++)
        t[y + i][x] = W[(size_t)(bk + y + i) * D_MODEL + bn + x];
    __syncthreads();
    #pragma unroll
    for (int i = 0; i < 4; i++)
        Wt[(size_t)(bn + y + i) * D_MODEL + bk + x] = __float2half(t[x][y + i]);
}

__global__ __launch_bounds__(256)
void transpose_h_kernel(const float* __restrict__ W, __half* __restrict__ Wt,
                        int Kd, int N)
{
    __shared__ float t[32][33];
    const int bn = blockIdx.x * 32;
    const int bk = blockIdx.y * 32;
    const int x = threadIdx.x & 31;
    const int y = (threadIdx.x >> 5) * 4;
    #pragma unroll
    for (int i = 0; i < 4; i++)
        t[y + i][x] = W[(size_t)(bk + y + i) * N + bn + x];
    __syncthreads();
    #pragma unroll
    for (int i = 0; i < 4; i++)
        Wt[(size_t)(bn + y + i) * Kd + bk + x] = __float2half(t[x][y + i]);
}

// Fused prep: blocks [0,2048) convert x -> xh; blocks [2048,2060) pack bias.
__global__ __launch_bounds__(256)
void prep_kernel(const float* __restrict__ in, __half* __restrict__ out,
                 const float* __restrict__ bq, const float* __restrict__ bk,
                 const float* __restrict__ bv, float* __restrict__ ob)
{
    const int bx = blockIdx.x;
    if (bx < 2048) {
        const int i = bx * 256 + threadIdx.x;
        float4 a = ((const float4*)in)[2 * i];
        float4 b = ((const float4*)in)[2 * i + 1];
        uint4 o;
        o.x = pack_h2(a.x, a.y); o.y = pack_h2(a.z, a.w);
        o.z = pack_h2(b.x, b.y); o.w = pack_h2(b.z, b.w);
        ((uint4*)out)[i] = o;
    } else {
        const int i = (bx - 2048) * 256 + threadIdx.x;
        float v = (i < 1024) ? bq[i] : (i < 2048) ? bk[i - 1024] : bv[i - 2048];
        ob[i] = v;
    }
}

// ---------------------------------------------------------------------------
// fp16 mma.sync GEMM (R13 3-stage pipeline — unchanged, proven).
// ---------------------------------------------------------------------------
#define GSTR 36
#define GOP  (128 * GSTR)
#define STGW (2 * GOP)
#define GEMM_SMEM_BYTES (3 * STGW * 4)    // 110592

__global__ __launch_bounds__(128)
void gemm_f16(const __half* __restrict__ A,
              const __half* __restrict__ Bt,
              const float* __restrict__ bias,
              void* __restrict__ Cv,
              int Kd, int N, int mode)
{
    extern __shared__ uint32_t smg[];
    const uint32_t sbase = smem_u32(smg);

    const int tid  = threadIdx.x;
    const int lane = tid & 31;
    const int wid  = tid >> 5;
    const int g = lane >> 2;
    const int t = lane & 3;
    const int wm = wid & 1;
    const int wn = wid >> 1;
    const int row0 = blockIdx.y * 128;
    const int col0 = blockIdx.x * 128;

    float acc[4][8][4];
    #pragma unroll
    for (int mi = 0; mi < 4; mi++)
        #pragma unroll
        for (int ni = 0; ni < 8; ni++)
            #pragma unroll
            for (int j = 0; j < 4; j++) acc[mi][ni][j] = 0.f;

    uint32_t sdst[8];
    const __half* aP[8];
    const __half* bP[8];
    #pragma unroll
    for (int i = 0; i < 8; i++) {
        const int slot = tid + i * 128;
        const int r = slot >> 3, q = slot & 7;
        sdst[i] = (uint32_t)(r * GSTR + q * 4) * 4u;
        aP[i] = A  + (size_t)(row0 + r) * Kd + q * 8;
        bP[i] = Bt + (size_t)(col0 + r) * Kd + q * 8;
    }

    const int lane7 = lane & 7;
    const uint32_t aRow  = (uint32_t)(wm * 64 + lane7 + (lane & 8));
    const uint32_t aColW = (uint32_t)((lane >> 4) * 4);
    const uint32_t aOffB = (aRow * GSTR + aColW) * 4u;
    const uint32_t bRow  = (uint32_t)(wn * 64 + lane7 + ((lane >> 4) & 1) * 8);
    const uint32_t bColW = (uint32_t)(((lane >> 3) & 1) * 4);
    const uint32_t bOffB = (bRow * GSTR + bColW) * 4u + GOP * 4u;

    const int NC = Kd >> 6;

    #pragma unroll
    for (int i = 0; i < 8; i++) {
        CP16(sbase + sdst[i], aP[i]);
        CP16(sbase + GOP * 4u + sdst[i], bP[i]);
    }
    CP_COMMIT();
    {
        const uint32_t st = (uint32_t)STGW * 4u;
        #pragma unroll
        for (int i = 0; i < 8; i++) {
            CP16(sbase + st + sdst[i], aP[i] + 64);
            CP16(sbase + st + GOP * 4u + sdst[i], bP[i] + 64);
        }
        CP_COMMIT();
    }

    for (int c = 0; c < NC; c++) {
        CP_WAITG1();
        __syncthreads();

        const uint32_t stg = sbase + (uint32_t)(c % 3) * ((uint32_t)STGW * 4u);
        const uint32_t aBase = stg + aOffB;
        const uint32_t bBase = stg + bOffB;

        #pragma unroll
        for (int ks = 0; ks < 4; ks++) {
            const uint32_t kOff = (uint32_t)(ks * 8) * 4u;
            uint32_t af[4][4];
            #pragma unroll
            for (int mi = 0; mi < 4; mi++) {
                LDSM_X4(af[mi][0], af[mi][1], af[mi][2], af[mi][3],
                        aBase + (uint32_t)(mi * 16 * GSTR) * 4u + kOff);
            }
            uint32_t bf[8][2];
            #pragma unroll
            for (int pr = 0; pr < 4; pr++) {
                LDSM_X4(bf[2 * pr][0], bf[2 * pr][1], bf[2 * pr + 1][0], bf[2 * pr + 1][1],
                        bBase + (uint32_t)(pr * 16 * GSTR) * 4u + kOff);
            }
            #pragma unroll
            for (int ni = 0; ni < 8; ni++)
                #pragma unroll
                for (int mi = 0; mi < 4; mi++)
                    mma_f16(acc[mi][ni], af[mi], bf[ni][0], bf[ni][1]);
        }

        if (c + 2 < NC) {
            const int ko = (c + 2) * 64;
            const uint32_t st = (uint32_t)((c + 2) % 3) * ((uint32_t)STGW * 4u);
            #pragma unroll
            for (int i = 0; i < 8; i++) {
                CP16(sbase + st + sdst[i], aP[i] + ko);
                CP16(sbase + st + GOP * 4u + sdst[i], bP[i] + ko);
            }
            CP_COMMIT();
        }
    }

    #pragma unroll
    for (int mi = 0; mi < 4; mi++) {
        const int r0 = row0 + wm * 64 + mi * 16 + g;
        #pragma unroll
        for (int ni = 0; ni < 8; ni++) {
            const int col = col0 + wn * 64 + ni * 8 + 2 * t;
            float2 bb = *(const float2*)&bias[col];
            float v00 = acc[mi][ni][0] + bb.x;
            float v01 = acc[mi][ni][1] + bb.y;
            float v10 = acc[mi][ni][2] + bb.x;
            float v11 = acc[mi][ni][3] + bb.y;
            if (mode == 0) {
                float* C = (float*)Cv;
                float2 o0 = {v00, v01}, o1 = {v10, v11};
                *(float2*)&C[(size_t)r0 * N + col]       = o0;
                *(float2*)&C[(size_t)(r0 + 8) * N + col] = o1;
            } else {
                if (mode == 1) {
                    v00 = fmaxf(v00, 0.f); v01 = fmaxf(v01, 0.f);
                    v10 = fmaxf(v10, 0.f); v11 = fmaxf(v11, 0.f);
                }
                __half* C = (__half*)Cv;
                *(uint32_t*)&C[(size_t)r0 * N + col]       = pack_h2(v00, v01);
                *(uint32_t*)&C[(size_t)(r0 + 8) * N + col] = pack_h2(v10, v11);
            }
        }
    }
}

// ---------------------------------------------------------------------------
// fp16 flash attention v2:
//  - P passes C-fragment -> A-fragment in REGISTERS (same-thread identity;
//    removes 16 STS + 16 LDS + 2 syncwarp per tile)
//  - mask via warp-ballot bitmask (2 uint32 per tile; removes 16 LDS/thread)
// ---------------------------------------------------------------------------
#define ASTR 44
#define VSTR 72

__global__ __launch_bounds__(128)
void attn_f16(const __half* __restrict__ QKV,
              const int*   __restrict__ mask,
              __half* __restrict__ O)
{
    __shared__ uint32_t Qs[64 * ASTR];
    __shared__ uint32_t Ks[64 * ASTR];
    __shared__ uint32_t VT[32 * VSTR];
    __shared__ uint32_t msb[2];

    const int b  = blockIdx.z;
    const int h  = blockIdx.y;
    const int q0 = blockIdx.x * 64;
    const int tid  = threadIdx.x;
    const int lane = tid & 31;
    const int wid  = tid >> 5;
    const int g = lane >> 2;
    const int t = lane & 3;

    const int qc = h * HEAD_DIM;
    const int kc = D_MODEL + h * HEAD_DIM;
    const int vc = 2 * D_MODEL + h * HEAD_DIM;

    #pragma unroll
    for (int i = 0; i < 4; i++) {
        const int slot = tid + i * 128;
        const int r = slot >> 3, q8 = slot & 7;
        uint4 v = *(const uint4*)(QKV + (size_t)(b * S_ + q0 + r) * QKV_N + qc + q8 * 8);
        *(uint4*)&Qs[r * ASTR + q8 * 4] = v;
    }
    __syncthreads();

    const int mrow = wid * 16 + g;
    uint32_t qf[4][4];
    #pragma unroll
    for (int ks = 0; ks < 4; ks++) {
        qf[ks][0] = Qs[mrow * ASTR + ks * 8 + t];
        qf[ks][1] = Qs[(mrow + 8) * ASTR + ks * 8 + t];
        qf[ks][2] = Qs[mrow * ASTR + ks * 8 + 4 + t];
        qf[ks][3] = Qs[(mrow + 8) * ASTR + ks * 8 + 4 + t];
    }
    __syncthreads();

    float o[8][4];
    #pragma unroll
    for (int ni = 0; ni < 8; ni++)
        #pragma unroll
        for (int j = 0; j < 4; j++) o[ni][j] = 0.f;
    float m0 = -1e30f, m1 = -1e30f, l0 = 0.f, l1 = 0.f;

    const int vj = tid & 31;
    const int vdh = (tid >> 5) * 16;

    for (int kt = 0; kt < S_; kt += 64) {
        // K tile
        #pragma unroll
        for (int i = 0; i < 4; i++) {
            const int slot = tid + i * 128;
            const int r = slot >> 3, q8 = slot & 7;
            uint4 v = *(const uint4*)(QKV + (size_t)(b * S_ + kt + r) * QKV_N + kc + q8 * 8);
            *(uint4*)&Ks[r * ASTR + q8 * 4] = v;
        }
        // V tile -> VT (zip rows 2j, 2j+1)
        {
            const __half* v0p = QKV + (size_t)(b * S_ + kt + 2 * vj) * QKV_N + vc + vdh;
            const __half* v1p = v0p + QKV_N;
            uint4 r0a = *(const uint4*)(v0p);
            uint4 r0b = *(const uint4*)(v0p + 8);
            uint4 r1a = *(const uint4*)(v1p);
            uint4 r1b = *(const uint4*)(v1p + 8);
            uint32_t* dst = &VT[vj * VSTR + vdh];
            uint4 z;
            z.x = __byte_perm(r0a.x, r1a.x, 0x5410);
            z.y = __byte_perm(r0a.x, r1a.x, 0x7632);
            z.z = __byte_perm(r0a.y, r1a.y, 0x5410);
            z.w = __byte_perm(r0a.y, r1a.y, 0x7632);
            *(uint4*)dst = z;
            z.x = __byte_perm(r0a.z, r1a.z, 0x5410);
            z.y = __byte_perm(r0a.z, r1a.z, 0x7632);
            z.z = __byte_perm(r0a.w, r1a.w, 0x5410);
            z.w = __byte_perm(r0a.w, r1a.w, 0x7632);
            *(uint4*)(dst + 4) = z;
            z.x = __byte_perm(r0b.x, r1b.x, 0x5410);
            z.y = __byte_perm(r0b.x, r1b.x, 0x7632);
            z.z = __byte_perm(r0b.y, r1b.y, 0x5410);
            z.w = __byte_perm(r0b.y, r1b.y, 0x7632);
            *(uint4*)(dst + 8) = z;
            z.x = __byte_perm(r0b.z, r1b.z, 0x5410);
            z.y = __byte_perm(r0b.z, r1b.z, 0x7632);
            z.z = __byte_perm(r0b.w, r1b.w, 0x5410);
            z.w = __byte_perm(r0b.w, r1b.w, 0x7632);
            *(uint4*)(dst + 12) = z;
        }
        // Mask ballot: warps 0,1 cover keys 0..63 of this tile
        if (tid < 64) {
            const int mv = mask[b * S_ + kt + tid];
            const uint32_t bits = __ballot_sync(0xffffffffu, mv != 0);
            if (lane == 0) msb[wid] = bits;
        }
        __syncthreads();

        const uint32_t mw0 = msb[0];
        const uint32_t mw1 = msb[1];

        // S = Q @ K^T
        float s[8][4];
        #pragma unroll
        for (int ni = 0; ni < 8; ni++)
            #pragma unroll
            for (int j = 0; j < 4; j++) s[ni][j] = 0.f;

        #pragma unroll
        for (int ks = 0; ks < 4; ks++) {
            #pragma unroll
            for (int ni = 0; ni < 8; ni++) {
                const int n0 = ni * 8 + g;
                const uint32_t b0 = Ks[n0 * ASTR + ks * 8 + t];
                const uint32_t b1 = Ks[n0 * ASTR + ks * 8 + 4 + t];
                mma_f16(s[ni], qf[ks], b0, b1);
            }
        }

        // scale + mask(bitmask) + online softmax
        float rmax0 = -1e30f, rmax1 = -1e30f;
        #pragma unroll
        for (int ni = 0; ni < 8; ni++) {
            const uint32_t word = (ni < 4) ? mw0 : mw1;
            const int shift = (ni & 3) * 8 + 2 * t;
            const bool k0 = (word >> shift) & 1u;
            const bool k1 = (word >> (shift + 1)) & 1u;
            float v0 = s[ni][0] * 0.125f; if (!k0) v0 = -1e9f;
            float v1 = s[ni][1] * 0.125f; if (!k1) v1 = -1e9f;
            float v2 = s[ni][2] * 0.125f; if (!k0) v2 = -1e9f;
            float v3 = s[ni][3] * 0.125f; if (!k1) v3 = -1e9f;
            s[ni][0] = v0; s[ni][1] = v1; s[ni][2] = v2; s[ni][3] = v3;
            rmax0 = fmaxf(rmax0, fmaxf(v0, v1));
            rmax1 = fmaxf(rmax1, fmaxf(v2, v3));
        }
        rmax0 = fmaxf(rmax0, __shfl_xor_sync(0xffffffffu, rmax0, 1));
        rmax0 = fmaxf(rmax0, __shfl_xor_sync(0xffffffffu, rmax0, 2));
        rmax1 = fmaxf(rmax1, __shfl_xor_sync(0xffffffffu, rmax1, 1));
        rmax1 = fmaxf(rmax1, __shfl_xor_sync(0xffffffffu, rmax1, 2));

        const float mn0 = fmaxf(m0, rmax0);
        const float mn1 = fmaxf(m1, rmax1);
        const float c0 = __expf(m0 - mn0);
        const float c1 = __expf(m1 - mn1);

        float rs0 = 0.f, rs1 = 0.f;
        #pragma unroll
        for (int ni = 0; ni < 8; ni++) {
            float p0 = __expf(s[ni][0] - mn0);
            float p1 = __expf(s[ni][1] - mn0);
            float p2 = __expf(s[ni][2] - mn1);
            float p3 = __expf(s[ni][3] - mn1);
            s[ni][0] = p0; s[ni][1] = p1; s[ni][2] = p2; s[ni][3] = p3;
            rs0 += p0 + p1;
            rs1 += p2 + p3;
        }
        rs0 += __shfl_xor_sync(0xffffffffu, rs0, 1);
        rs0 += __shfl_xor_sync(0xffffffffu, rs0, 2);
        rs1 += __shfl_xor_sync(0xffffffffu, rs1, 1);
        rs1 += __shfl_xor_sync(0xffffffffu, rs1, 2);

        l0 = l0 * c0 + rs0;
        l1 = l1 * c1 + rs1;
        #pragma unroll
        for (int ni = 0; ni < 8; ni++) {
            o[ni][0] *= c0; o[ni][1] *= c0;
            o[ni][2] *= c1; o[ni][3] *= c1;
        }
        m0 = mn0; m1 = mn1;

        // O += P @ V — P passed directly as A fragments (same-thread identity)
        #pragma unroll
        for (int ks = 0; ks < 4; ks++) {
            uint32_t a[4];
            a[0] = pack_h2(s[2 * ks][0],     s[2 * ks][1]);
            a[1] = pack_h2(s[2 * ks][2],     s[2 * ks][3]);
            a[2] = pack_h2(s[2 * ks + 1][0], s[2 * ks + 1][1]);
            a[3] = pack_h2(s[2 * ks + 1][2], s[2 * ks + 1][3]);
            #pragma unroll
            for (int ni = 0; ni < 8; ni++) {
                const uint32_t b0 = VT[(ks * 8 + t) * VSTR + ni * 8 + g];
                const uint32_t b1 = VT[(ks * 8 + 4 + t) * VSTR + ni * 8 + g];
                mma_f16(o[ni], a, b0, b1);
            }
        }
        __syncthreads();
    }

    const float inv0 = 1.f / l0;
    const float inv1 = 1.f / l1;
    const size_t r0 = (size_t)(b * S_ + q0 + mrow) * D_MODEL + h * HEAD_DIM;
    const size_t r1 = (size_t)(b * S_ + q0 + mrow + 8) * D_MODEL + h * HEAD_DIM;
    #pragma unroll
    for (int ni = 0; ni < 8; ni++) {
        const int col = ni * 8 + 2 * t;
        *(uint32_t*)&O[r0 + col] = pack_h2(o[ni][0] * inv0, o[ni][1] * inv0);
        *(uint32_t*)&O[r1 + col] = pack_h2(o[ni][2] * inv1, o[ni][3] * inv1);
    }
}

// ---------------------------------------------------------------------------
// Residual add + LayerNorm; optional fp16 second output
// ---------------------------------------------------------------------------
__global__ __launch_bounds__(256)
void add_ln_kernel(const float* __restrict__ X,
                   const float* __restrict__ Y,
                   const float* __restrict__ g,
                   const float* __restrict__ beta,
                   float* __restrict__ out,
                   __half* __restrict__ outh)
{
    const int row = blockIdx.x;
    const int t = threadIdx.x;
    const float4 a = ((const float4*)(X + (size_t)row * D_MODEL))[t];
    const float4 c = ((const float4*)(Y + (size_t)row * D_MODEL))[t];
    const float v0 = a.x + c.x, v1 = a.y + c.y, v2 = a.z + c.z, v3 = a.w + c.w;

    float s  = v0 + v1 + v2 + v3;
    float ss = v0 * v0 + v1 * v1 + v2 * v2 + v3 * v3;

    #pragma unroll
    for (int off = 16; off; off >>= 1) {
        s  += __shfl_xor_sync(0xffffffffu, s,  off);
        ss += __shfl_xor_sync(0xffffffffu, ss, off);
    }
    __shared__ float ws[8], wss[8];
    const int w = t >> 5;
    if ((t & 31) == 0) { ws[w] = s; wss[w] = ss; }
    __syncthreads();

    float stot = 0.f, sstot = 0.f;
    #pragma unroll
    for (int i = 0; i < 8; i++) { stot += ws[i]; sstot += wss[i]; }

    const float mean = stot * (1.f / 1024.f);
    const float var  = sstot * (1.f / 1024.f) - mean * mean;
    const float r    = rsqrtf(var + 1e-5f);

    const float4 gg = ((const float4*)g)[t];
    const float4 bb = ((const float4*)beta)[t];
    float4 o;
    o.x = (v0 - mean) * r * gg.x + bb.x;
    o.y = (v1 - mean) * r * gg.y + bb.y;
    o.z = (v2 - mean) * r * gg.z + bb.z;
    o.w = (v3 - mean) * r * gg.w + bb.w;
    ((float4*)(out + (size_t)row * D_MODEL))[t] = o;
    if (outh) {
        uint2 q;
        q.x = pack_h2(o.x, o.y);
        q.y = pack_h2(o.z, o.w);
        ((uint2*)(outh + (size_t)row * D_MODEL))[t] = q;
    }
}

// ---------------------------------------------------------------------------
// Launch — attn_f16 in profiled slot #4
// ---------------------------------------------------------------------------
extern "C" void kernel_launch(void* const* d_in, const int* in_sizes, int n_in,
                              void* d_out, int out_size)
{
    const float* x    = (const float*)d_in[0];
    const int*   mask = (const int*)  d_in[1];
    const float* wq   = (const float*)d_in[2];
    const float* bq   = (const float*)d_in[3];
    const float* wk   = (const float*)d_in[4];
    const float* bk   = (const float*)d_in[5];
    const float* wv   = (const float*)d_in[6];
    const float* bv   = (const float*)d_in[7];
    const float* wo   = (const float*)d_in[8];
    const float* bo   = (const float*)d_in[9];
    const float* w1   = (const float*)d_in[10];
    const float* b1   = (const float*)d_in[11];
    const float* w2   = (const float*)d_in[12];
    const float* b2   = (const float*)d_in[13];
    const float* ln1g = (const float*)d_in[14];
    const float* ln1b = (const float*)d_in[15];
    const float* ln2g = (const float*)d_in[16];
    const float* ln2b = (const float*)d_in[17];

    __half *xh, *qkv, *ap, *x1h, *f1p;
    float *pp, *x1p, *f2p, *bqkv;
    __half *wqkvt, *wot, *w1t, *w2t;
    cudaGetSymbolAddress((void**)&xh,    g_xh);
    cudaGetSymbolAddress((void**)&qkv,   g_qkv);
    cudaGetSymbolAddress((void**)&ap,    g_attn);
    cudaGetSymbolAddress((void**)&pp,    g_proj);
    cudaGetSymbolAddress((void**)&x1p,   g_x1);
    cudaGetSymbolAddress((void**)&x1h,   g_x1h);
    cudaGetSymbolAddress((void**)&f1p,   g_ff1);
    cudaGetSymbolAddress((void**)&f2p,   g_ff2);
    cudaGetSymbolAddress((void**)&wqkvt, g_wqkvt);
    cudaGetSymbolAddress((void**)&wot,   g_wot);
    cudaGetSymbolAddress((void**)&w1t,   g_w1t);
    cudaGetSymbolAddress((void**)&w2t,   g_w2t);
    cudaGetSymbolAddress((void**)&bqkv,  g_bqkv);

    static int attr_set = 0;
    if (!attr_set) {
        cudaFuncSetAttribute(gemm_f16,
                             cudaFuncAttributeMaxDynamicSharedMemorySize,
                             GEMM_SMEM_BYTES);
        cudaFuncSetAttribute(gemm_f16,
                             cudaFuncAttributePreferredSharedMemoryCarveout,
                             cudaSharedmemCarveoutMaxShared);
        attr_set = 1;
    }

    // 1-2: QKV GEMM dependencies
    prep_kernel<<<2060, 256>>>(x, xh, bq, bk, bv, bqkv);
    transpose3_kernel<<<dim3(32, 32, 3), 256>>>(wq, wk, wv, wqkvt);

    // 3: fused QKV GEMM
    gemm_f16<<<dim3(QKV_N / 128, ROWS / 128), 128, GEMM_SMEM_BYTES>>>(
        xh, wqkvt, bqkv, qkv, D_MODEL, QKV_N, 2);

    // 4 (profiled): attention
    attn_f16<<<dim3(S_ / 64, NUM_HEADS, B_), 128>>>(qkv, mask, ap);

    transpose_h_kernel<<<dim3(D_MODEL / 32, D_MODEL / 32), 256>>>(wo, wot, D_MODEL, D_MODEL);
    transpose_h_kernel<<<dim3(D_FF / 32,    D_MODEL / 32), 256>>>(w1, w1t, D_MODEL, D_FF);
    transpose_h_kernel<<<dim3(D_MODEL / 32, D_FF / 32),    256>>>(w2, w2t, D_FF, D_MODEL);

    gemm_f16<<<dim3(D_MODEL / 128, ROWS / 128), 128, GEMM_SMEM_BYTES>>>(
        ap, wot, bo, pp, D_MODEL, D_MODEL, 0);
    add_ln_kernel<<<ROWS, 256>>>(x, pp, ln1g, ln1b, x1p, x1h);

    gemm_f16<<<dim3(D_FF / 128, ROWS / 128), 128, GEMM_SMEM_BYTES>>>(
        x1h, w1t, b1, f1p, D_MODEL, D_FF, 1);
    gemm_f16<<<dim3(D_MODEL / 128, ROWS / 128), 128, GEMM_SMEM_BYTES>>>(
        f1p, w2t, b2, f2p, D_FF, D_MODEL, 0);
    add_ln_kernel<<<ROWS, 256>>>(x1p, f2p, ln2g, ln2b, (float*)d_out, (__half*)0);
}

// round 15
// speedup vs baseline: 1.6934x; 1.0818x over previous
#include <cuda_runtime.h>
#include <cuda_fp16.h>
#include <cstdint>

#define D_MODEL   1024
#define NUM_HEADS 16
#define HEAD_DIM  64
#define D_FF      4096
#define B_        2
#define S_        2048
#define ROWS      (B_ * S_)   // 4096
#define QKV_N     (3 * D_MODEL)

// ---------------------------------------------------------------------------
// Scratch (device globals; no allocation allowed)
// ---------------------------------------------------------------------------
__device__ __half g_xh  [ROWS * D_MODEL];
__device__ __half g_qkv [ROWS * QKV_N];
__device__ __half g_attn[ROWS * D_MODEL];
__device__ float  g_proj[ROWS * D_MODEL];
__device__ float  g_x1  [ROWS * D_MODEL];
__device__ __half g_x1h [ROWS * D_MODEL];
__device__ __half g_ff1 [ROWS * D_FF];
__device__ float  g_ff2 [ROWS * D_MODEL];
__device__ __half g_wqkvt[QKV_N * D_MODEL];
__device__ __half g_wot  [D_MODEL * D_MODEL];
__device__ __half g_w1t  [D_FF * D_MODEL];
__device__ __half g_w2t  [D_MODEL * D_FF];
__device__ float  g_bqkv [QKV_N];

__device__ __forceinline__ uint32_t smem_u32(const void* p) {
    uint32_t a;
    asm("{ .reg .u64 t; cvta.to.shared.u64 t, %1; cvt.u32.u64 %0, t; }"
        : "=r"(a) : "l"(p));
    return a;
}
// fp16 mma m16n8k16, fp32 accum
__device__ __forceinline__ void mma_f16(float* d, const uint32_t* a,
                                        uint32_t b0, uint32_t b1) {
    asm volatile(
        "mma.sync.aligned.m16n8k16.row.col.f32.f16.f16.f32 "
        "{%0,%1,%2,%3}, {%4,%5,%6,%7}, {%8,%9}, {%0,%1,%2,%3};"
        : "+f"(d[0]), "+f"(d[1]), "+f"(d[2]), "+f"(d[3])
        : "r"(a[0]), "r"(a[1]), "r"(a[2]), "r"(a[3]), "r"(b0), "r"(b1));
}
#define LDSM_X4(R0, R1, R2, R3, saddr) \
    asm volatile("ldmatrix.sync.aligned.m8n8.x4.shared.b16 {%0,%1,%2,%3}, [%4];" \
        : "=r"(R0), "=r"(R1), "=r"(R2), "=r"(R3) : "r"(saddr))
#define CP16(dst, src) \
    asm volatile("cp.async.cg.shared.global [%0], [%1], 16;" \
                 :: "r"(dst), "l"(src) : "memory")
#define CP_COMMIT() asm volatile("cp.async.commit_group;" ::: "memory")
#define CP_WAITG1() asm volatile("cp.async.wait_group 1;" ::: "memory")

__device__ __forceinline__ uint32_t pack_h2(float lo, float hi) {
    __half2 h = __floats2half2_rn(lo, hi);
    return *(uint32_t*)&h;
}

// ---------------------------------------------------------------------------
// Weight prep
// ---------------------------------------------------------------------------
__global__ __launch_bounds__(256)
void transpose3_kernel(const float* __restrict__ wq, const float* __restrict__ wk,
                       const float* __restrict__ wv, __half* __restrict__ out)
{
    __shared__ float t[32][33];
    const float* W = (blockIdx.z == 0) ? wq : (blockIdx.z == 1) ? wk : wv;
    __half* Wt = out + (size_t)blockIdx.z * D_MODEL * D_MODEL;
    const int bn = blockIdx.x * 32;
    const int bk = blockIdx.y * 32;
    const int x = threadIdx.x & 31;
    const int y = (threadIdx.x >> 5) * 4;
    #pragma unroll
    for (int i = 0; i < 4; i++)
        t[y + i][x] = W[(size_t)(bk + y + i) * D_MODEL + bn + x];
    __syncthreads();
    #pragma unroll
    for (int i = 0; i < 4; i++)
        Wt[(size_t)(bn + y + i) * D_MODEL + bk + x] = __float2half(t[x][y + i]);
}

__global__ __launch_bounds__(256)
void transpose_h_kernel(const float* __restrict__ W, __half* __restrict__ Wt,
                        int Kd, int N)
{
    __shared__ float t[32][33];
    const int bn = blockIdx.x * 32;
    const int bk = blockIdx.y * 32;
    const int x = threadIdx.x & 31;
    const int y = (threadIdx.x >> 5) * 4;
    #pragma unroll
    for (int i = 0; i < 4; i++)
        t[y + i][x] = W[(size_t)(bk + y + i) * N + bn + x];
    __syncthreads();
    #pragma unroll
    for (int i = 0; i < 4; i++)
        Wt[(size_t)(bn + y + i) * Kd + bk + x] = __float2half(t[x][y + i]);
}

// Fused prep: blocks [0,2048) convert x -> xh; blocks [2048,2060) pack bias.
__global__ __launch_bounds__(256)
void prep_kernel(const float* __restrict__ in, __half* __restrict__ out,
                 const float* __restrict__ bq, const float* __restrict__ bk,
                 const float* __restrict__ bv, float* __restrict__ ob)
{
    const int bx = blockIdx.x;
    if (bx < 2048) {
        const int i = bx * 256 + threadIdx.x;
        float4 a = ((const float4*)in)[2 * i];
        float4 b = ((const float4*)in)[2 * i + 1];
        uint4 o;
        o.x = pack_h2(a.x, a.y); o.y = pack_h2(a.z, a.w);
        o.z = pack_h2(b.x, b.y); o.w = pack_h2(b.z, b.w);
        ((uint4*)out)[i] = o;
    } else {
        const int i = (bx - 2048) * 256 + threadIdx.x;
        float v = (i < 1024) ? bq[i] : (i < 2048) ? bk[i - 1024] : bv[i - 2048];
        ob[i] = v;
    }
}

// ---------------------------------------------------------------------------
// fp16 mma.sync GEMM (R13 3-stage pipeline — unchanged, proven).
// ---------------------------------------------------------------------------
#define GSTR 36
#define GOP  (128 * GSTR)
#define STGW (2 * GOP)
#define GEMM_SMEM_BYTES (3 * STGW * 4)    // 110592

__global__ __launch_bounds__(128)
void gemm_f16(const __half* __restrict__ A,
              const __half* __restrict__ Bt,
              const float* __restrict__ bias,
              void* __restrict__ Cv,
              int Kd, int N, int mode)
{
    extern __shared__ uint32_t smg[];
    const uint32_t sbase = smem_u32(smg);

    const int tid  = threadIdx.x;
    const int lane = tid & 31;
    const int wid  = tid >> 5;
    const int g = lane >> 2;
    const int t = lane & 3;
    const int wm = wid & 1;
    const int wn = wid >> 1;
    const int row0 = blockIdx.y * 128;
    const int col0 = blockIdx.x * 128;

    float acc[4][8][4];
    #pragma unroll
    for (int mi = 0; mi < 4; mi++)
        #pragma unroll
        for (int ni = 0; ni < 8; ni++)
            #pragma unroll
            for (int j = 0; j < 4; j++) acc[mi][ni][j] = 0.f;

    uint32_t sdst[8];
    const __half* aP[8];
    const __half* bP[8];
    #pragma unroll
    for (int i = 0; i < 8; i++) {
        const int slot = tid + i * 128;
        const int r = slot >> 3, q = slot & 7;
        sdst[i] = (uint32_t)(r * GSTR + q * 4) * 4u;
        aP[i] = A  + (size_t)(row0 + r) * Kd + q * 8;
        bP[i] = Bt + (size_t)(col0 + r) * Kd + q * 8;
    }

    const int lane7 = lane & 7;
    const uint32_t aRow  = (uint32_t)(wm * 64 + lane7 + (lane & 8));
    const uint32_t aColW = (uint32_t)((lane >> 4) * 4);
    const uint32_t aOffB = (aRow * GSTR + aColW) * 4u;
    const uint32_t bRow  = (uint32_t)(wn * 64 + lane7 + ((lane >> 4) & 1) * 8);
    const uint32_t bColW = (uint32_t)(((lane >> 3) & 1) * 4);
    const uint32_t bOffB = (bRow * GSTR + bColW) * 4u + GOP * 4u;

    const int NC = Kd >> 6;

    #pragma unroll
    for (int i = 0; i < 8; i++) {
        CP16(sbase + sdst[i], aP[i]);
        CP16(sbase + GOP * 4u + sdst[i], bP[i]);
    }
    CP_COMMIT();
    {
        const uint32_t st = (uint32_t)STGW * 4u;
        #pragma unroll
        for (int i = 0; i < 8; i++) {
            CP16(sbase + st + sdst[i], aP[i] + 64);
            CP16(sbase + st + GOP * 4u + sdst[i], bP[i] + 64);
        }
        CP_COMMIT();
    }

    for (int c = 0; c < NC; c++) {
        CP_WAITG1();
        __syncthreads();

        const uint32_t stg = sbase + (uint32_t)(c % 3) * ((uint32_t)STGW * 4u);
        const uint32_t aBase = stg + aOffB;
        const uint32_t bBase = stg + bOffB;

        #pragma unroll
        for (int ks = 0; ks < 4; ks++) {
            const uint32_t kOff = (uint32_t)(ks * 8) * 4u;
            uint32_t af[4][4];
            #pragma unroll
            for (int mi = 0; mi < 4; mi++) {
                LDSM_X4(af[mi][0], af[mi][1], af[mi][2], af[mi][3],
                        aBase + (uint32_t)(mi * 16 * GSTR) * 4u + kOff);
            }
            uint32_t bf[8][2];
            #pragma unroll
            for (int pr = 0; pr < 4; pr++) {
                LDSM_X4(bf[2 * pr][0], bf[2 * pr][1], bf[2 * pr + 1][0], bf[2 * pr + 1][1],
                        bBase + (uint32_t)(pr * 16 * GSTR) * 4u + kOff);
            }
            #pragma unroll
            for (int ni = 0; ni < 8; ni++)
                #pragma unroll
                for (int mi = 0; mi < 4; mi++)
                    mma_f16(acc[mi][ni], af[mi], bf[ni][0], bf[ni][1]);
        }

        if (c + 2 < NC) {
            const int ko = (c + 2) * 64;
            const uint32_t st = (uint32_t)((c + 2) % 3) * ((uint32_t)STGW * 4u);
            #pragma unroll
            for (int i = 0; i < 8; i++) {
                CP16(sbase + st + sdst[i], aP[i] + ko);
                CP16(sbase + st + GOP * 4u + sdst[i], bP[i] + ko);
            }
            CP_COMMIT();
        }
    }

    #pragma unroll
    for (int mi = 0; mi < 4; mi++) {
        const int r0 = row0 + wm * 64 + mi * 16 + g;
        #pragma unroll
        for (int ni = 0; ni < 8; ni++) {
            const int col = col0 + wn * 64 + ni * 8 + 2 * t;
            float2 bb = *(const float2*)&bias[col];
            float v00 = acc[mi][ni][0] + bb.x;
            float v01 = acc[mi][ni][1] + bb.y;
            float v10 = acc[mi][ni][2] + bb.x;
            float v11 = acc[mi][ni][3] + bb.y;
            if (mode == 0) {
                float* C = (float*)Cv;
                float2 o0 = {v00, v01}, o1 = {v10, v11};
                *(float2*)&C[(size_t)r0 * N + col]       = o0;
                *(float2*)&C[(size_t)(r0 + 8) * N + col] = o1;
            } else {
                if (mode == 1) {
                    v00 = fmaxf(v00, 0.f); v01 = fmaxf(v01, 0.f);
                    v10 = fmaxf(v10, 0.f); v11 = fmaxf(v11, 0.f);
                }
                __half* C = (__half*)Cv;
                *(uint32_t*)&C[(size_t)r0 * N + col]       = pack_h2(v00, v01);
                *(uint32_t*)&C[(size_t)(r0 + 8) * N + col] = pack_h2(v10, v11);
            }
        }
    }
}

// ---------------------------------------------------------------------------
// fp16 flash attention v3: 128 q-rows per CTA, 32 q-rows per warp (2 m16
// tiles). Every K/V B-fragment load now feeds 2 mmas; K/V tile loads serve
// 128 q-rows. Halves per-q L1/smem bytes vs v2. Register P pass + ballot
// mask retained.
// ---------------------------------------------------------------------------
#define ASTR 44
#define VSTR 72

__global__ __launch_bounds__(128)
void attn_f16(const __half* __restrict__ QKV,
              const int*   __restrict__ mask,
              __half* __restrict__ O)
{
    __shared__ uint32_t Qs[128 * ASTR];
    __shared__ uint32_t Ks[64 * ASTR];
    __shared__ uint32_t VT[32 * VSTR];
    __shared__ uint32_t msb[2];

    const int b  = blockIdx.z;
    const int h  = blockIdx.y;
    const int q0 = blockIdx.x * 128;
    const int tid  = threadIdx.x;
    const int lane = tid & 31;
    const int wid  = tid >> 5;
    const int g = lane >> 2;
    const int t = lane & 3;

    const int qc = h * HEAD_DIM;
    const int kc = D_MODEL + h * HEAD_DIM;
    const int vc = 2 * D_MODEL + h * HEAD_DIM;

    // Stage Q: 128 rows x 8 uint4
    #pragma unroll
    for (int i = 0; i < 8; i++) {
        const int slot = tid + i * 128;
        const int r = slot >> 3, q8 = slot & 7;
        uint4 v = *(const uint4*)(QKV + (size_t)(b * S_ + q0 + r) * QKV_N + qc + q8 * 8);
        *(uint4*)&Qs[r * ASTR + q8 * 4] = v;
    }
    __syncthreads();

    uint32_t qf[2][4][4];
    #pragma unroll
    for (int mi = 0; mi < 2; mi++) {
        const int mrow = wid * 32 + mi * 16 + g;
        #pragma unroll
        for (int ks = 0; ks < 4; ks++) {
            qf[mi][ks][0] = Qs[mrow * ASTR + ks * 8 + t];
            qf[mi][ks][1] = Qs[(mrow + 8) * ASTR + ks * 8 + t];
            qf[mi][ks][2] = Qs[mrow * ASTR + ks * 8 + 4 + t];
            qf[mi][ks][3] = Qs[(mrow + 8) * ASTR + ks * 8 + 4 + t];
        }
    }
    __syncthreads();

    float o[2][8][4];
    #pragma unroll
    for (int mi = 0; mi < 2; mi++)
        #pragma unroll
        for (int ni = 0; ni < 8; ni++)
            #pragma unroll
            for (int j = 0; j < 4; j++) o[mi][ni][j] = 0.f;
    float mx[2][2] = {{-1e30f, -1e30f}, {-1e30f, -1e30f}};
    float lv[2][2] = {{0.f, 0.f}, {0.f, 0.f}};

    const int vj = tid & 31;
    const int vdh = (tid >> 5) * 16;

    for (int kt = 0; kt < S_; kt += 64) {
        // K tile: 64 rows x 8 uint4
        #pragma unroll
        for (int i = 0; i < 4; i++) {
            const int slot = tid + i * 128;
            const int r = slot >> 3, q8 = slot & 7;
            uint4 v = *(const uint4*)(QKV + (size_t)(b * S_ + kt + r) * QKV_N + kc + q8 * 8);
            *(uint4*)&Ks[r * ASTR + q8 * 4] = v;
        }
        // V tile -> VT zip
        {
            const __half* v0p = QKV + (size_t)(b * S_ + kt + 2 * vj) * QKV_N + vc + vdh;
            const __half* v1p = v0p + QKV_N;
            uint4 r0a = *(const uint4*)(v0p);
            uint4 r0b = *(const uint4*)(v0p + 8);
            uint4 r1a = *(const uint4*)(v1p);
            uint4 r1b = *(const uint4*)(v1p + 8);
            uint32_t* dst = &VT[vj * VSTR + vdh];
            uint4 z;
            z.x = __byte_perm(r0a.x, r1a.x, 0x5410);
            z.y = __byte_perm(r0a.x, r1a.x, 0x7632);
            z.z = __byte_perm(r0a.y, r1a.y, 0x5410);
            z.w = __byte_perm(r0a.y, r1a.y, 0x7632);
            *(uint4*)dst = z;
            z.x = __byte_perm(r0a.z, r1a.z, 0x5410);
            z.y = __byte_perm(r0a.z, r1a.z, 0x7632);
            z.z = __byte_perm(r0a.w, r1a.w, 0x5410);
            z.w = __byte_perm(r0a.w, r1a.w, 0x7632);
            *(uint4*)(dst + 4) = z;
            z.x = __byte_perm(r0b.x, r1b.x, 0x5410);
            z.y = __byte_perm(r0b.x, r1b.x, 0x7632);
            z.z = __byte_perm(r0b.y, r1b.y, 0x5410);
            z.w = __byte_perm(r0b.y, r1b.y, 0x7632);
            *(uint4*)(dst + 8) = z;
            z.x = __byte_perm(r0b.z, r1b.z, 0x5410);
            z.y = __byte_perm(r0b.z, r1b.z, 0x7632);
            z.z = __byte_perm(r0b.w, r1b.w, 0x5410);
            z.w = __byte_perm(r0b.w, r1b.w, 0x7632);
            *(uint4*)(dst + 12) = z;
        }
        if (tid < 64) {
            const int mv = mask[b * S_ + kt + tid];
            const uint32_t bits = __ballot_sync(0xffffffffu, mv != 0);
            if (lane == 0) msb[wid] = bits;
        }
        __syncthreads();

        const uint32_t mw0 = msb[0];
        const uint32_t mw1 = msb[1];

        // S = Q @ K^T — each B fragment feeds both m-tiles
        float s[2][8][4];
        #pragma unroll
        for (int mi = 0; mi < 2; mi++)
            #pragma unroll
            for (int ni = 0; ni < 8; ni++)
                #pragma unroll
                for (int j = 0; j < 4; j++) s[mi][ni][j] = 0.f;

        #pragma unroll
        for (int ks = 0; ks < 4; ks++) {
            #pragma unroll
            for (int ni = 0; ni < 8; ni++) {
                const int n0 = ni * 8 + g;
                const uint32_t b0 = Ks[n0 * ASTR + ks * 8 + t];
                const uint32_t b1 = Ks[n0 * ASTR + ks * 8 + 4 + t];
                mma_f16(s[0][ni], qf[0][ks], b0, b1);
                mma_f16(s[1][ni], qf[1][ks], b0, b1);
            }
        }

        // scale + mask + online softmax (per m-tile)
        #pragma unroll
        for (int mi = 0; mi < 2; mi++) {
            float rmax0 = -1e30f, rmax1 = -1e30f;
            #pragma unroll
            for (int ni = 0; ni < 8; ni++) {
                const uint32_t word = (ni < 4) ? mw0 : mw1;
                const int shift = (ni & 3) * 8 + 2 * t;
                const bool k0 = (word >> shift) & 1u;
                const bool k1 = (word >> (shift + 1)) & 1u;
                float v0 = s[mi][ni][0] * 0.125f; if (!k0) v0 = -1e9f;
                float v1 = s[mi][ni][1] * 0.125f; if (!k1) v1 = -1e9f;
                float v2 = s[mi][ni][2] * 0.125f; if (!k0) v2 = -1e9f;
                float v3 = s[mi][ni][3] * 0.125f; if (!k1) v3 = -1e9f;
                s[mi][ni][0] = v0; s[mi][ni][1] = v1;
                s[mi][ni][2] = v2; s[mi][ni][3] = v3;
                rmax0 = fmaxf(rmax0, fmaxf(v0, v1));
                rmax1 = fmaxf(rmax1, fmaxf(v2, v3));
            }
            rmax0 = fmaxf(rmax0, __shfl_xor_sync(0xffffffffu, rmax0, 1));
            rmax0 = fmaxf(rmax0, __shfl_xor_sync(0xffffffffu, rmax0, 2));
            rmax1 = fmaxf(rmax1, __shfl_xor_sync(0xffffffffu, rmax1, 1));
            rmax1 = fmaxf(rmax1, __shfl_xor_sync(0xffffffffu, rmax1, 2));

            const float mn0 = fmaxf(mx[mi][0], rmax0);
            const float mn1 = fmaxf(mx[mi][1], rmax1);
            const float c0 = __expf(mx[mi][0] - mn0);
            const float c1 = __expf(mx[mi][1] - mn1);

            float rs0 = 0.f, rs1 = 0.f;
            #pragma unroll
            for (int ni = 0; ni < 8; ni++) {
                float p0 = __expf(s[mi][ni][0] - mn0);
                float p1 = __expf(s[mi][ni][1] - mn0);
                float p2 = __expf(s[mi][ni][2] - mn1);
                float p3 = __expf(s[mi][ni][3] - mn1);
                s[mi][ni][0] = p0; s[mi][ni][1] = p1;
                s[mi][ni][2] = p2; s[mi][ni][3] = p3;
                rs0 += p0 + p1;
                rs1 += p2 + p3;
            }
            rs0 += __shfl_xor_sync(0xffffffffu, rs0, 1);
            rs0 += __shfl_xor_sync(0xffffffffu, rs0, 2);
            rs1 += __shfl_xor_sync(0xffffffffu, rs1, 1);
            rs1 += __shfl_xor_sync(0xffffffffu, rs1, 2);

            lv[mi][0] = lv[mi][0] * c0 + rs0;
            lv[mi][1] = lv[mi][1] * c1 + rs1;
            #pragma unroll
            for (int ni = 0; ni < 8; ni++) {
                o[mi][ni][0] *= c0; o[mi][ni][1] *= c0;
                o[mi][ni][2] *= c1; o[mi][ni][3] *= c1;
            }
            mx[mi][0] = mn0; mx[mi][1] = mn1;
        }

        // O += P @ V — register P; each V fragment feeds both m-tiles
        #pragma unroll
        for (int ks = 0; ks < 4; ks++) {
            uint32_t a0[4], a1[4];
            a0[0] = pack_h2(s[0][2 * ks][0],     s[0][2 * ks][1]);
            a0[1] = pack_h2(s[0][2 * ks][2],     s[0][2 * ks][3]);
            a0[2] = pack_h2(s[0][2 * ks + 1][0], s[0][2 * ks + 1][1]);
            a0[3] = pack_h2(s[0][2 * ks + 1][2], s[0][2 * ks + 1][3]);
            a1[0] = pack_h2(s[1][2 * ks][0],     s[1][2 * ks][1]);
            a1[1] = pack_h2(s[1][2 * ks][2],     s[1][2 * ks][3]);
            a1[2] = pack_h2(s[1][2 * ks + 1][0], s[1][2 * ks + 1][1]);
            a1[3] = pack_h2(s[1][2 * ks + 1][2], s[1][2 * ks + 1][3]);
            #pragma unroll
            for (int ni = 0; ni < 8; ni++) {
                const uint32_t b0 = VT[(ks * 8 + t) * VSTR + ni * 8 + g];
                const uint32_t b1 = VT[(ks * 8 + 4 + t) * VSTR + ni * 8 + g];
                mma_f16(o[0][ni], a0, b0, b1);
                mma_f16(o[1][ni], a1, b0, b1);
            }
        }
        __syncthreads();
    }

    #pragma unroll
    for (int mi = 0; mi < 2; mi++) {
        const int mrow = wid * 32 + mi * 16 + g;
        const float inv0 = 1.f / lv[mi][0];
        const float inv1 = 1.f / lv[mi][1];
        const size_t r0 = (size_t)(b * S_ + q0 + mrow) * D_MODEL + h * HEAD_DIM;
        const size_t r1 = (size_t)(b * S_ + q0 + mrow + 8) * D_MODEL + h * HEAD_DIM;
        #pragma unroll
        for (int ni = 0; ni < 8; ni++) {
            const int col = ni * 8 + 2 * t;
            *(uint32_t*)&O[r0 + col] = pack_h2(o[mi][ni][0] * inv0, o[mi][ni][1] * inv0);
            *(uint32_t*)&O[r1 + col] = pack_h2(o[mi][ni][2] * inv1, o[mi][ni][3] * inv1);
        }
    }
}

// ---------------------------------------------------------------------------
// Residual add + LayerNorm; optional fp16 second output
// ---------------------------------------------------------------------------
__global__ __launch_bounds__(256)
void add_ln_kernel(const float* __restrict__ X,
                   const float* __restrict__ Y,
                   const float* __restrict__ g,
                   const float* __restrict__ beta,
                   float* __restrict__ out,
                   __half* __restrict__ outh)
{
    const int row = blockIdx.x;
    const int t = threadIdx.x;
    const float4 a = ((const float4*)(X + (size_t)row * D_MODEL))[t];
    const float4 c = ((const float4*)(Y + (size_t)row * D_MODEL))[t];
    const float v0 = a.x + c.x, v1 = a.y + c.y, v2 = a.z + c.z, v3 = a.w + c.w;

    float s  = v0 + v1 + v2 + v3;
    float ss = v0 * v0 + v1 * v1 + v2 * v2 + v3 * v3;

    #pragma unroll
    for (int off = 16; off; off >>= 1) {
        s  += __shfl_xor_sync(0xffffffffu, s,  off);
        ss += __shfl_xor_sync(0xffffffffu, ss, off);
    }
    __shared__ float ws[8], wss[8];
    const int w = t >> 5;
    if ((t & 31) == 0) { ws[w] = s; wss[w] = ss; }
    __syncthreads();

    float stot = 0.f, sstot = 0.f;
    #pragma unroll
    for (int i = 0; i < 8; i++) { stot += ws[i]; sstot += wss[i]; }

    const float mean = stot * (1.f / 1024.f);
    const float var  = sstot * (1.f / 1024.f) - mean * mean;
    const float r    = rsqrtf(var + 1e-5f);

    const float4 gg = ((const float4*)g)[t];
    const float4 bb = ((const float4*)beta)[t];
    float4 o;
    o.x = (v0 - mean) * r * gg.x + bb.x;
    o.y = (v1 - mean) * r * gg.y + bb.y;
    o.z = (v2 - mean) * r * gg.z + bb.z;
    o.w = (v3 - mean) * r * gg.w + bb.w;
    ((float4*)(out + (size_t)row * D_MODEL))[t] = o;
    if (outh) {
        uint2 q;
        q.x = pack_h2(o.x, o.y);
        q.y = pack_h2(o.z, o.w);
        ((uint2*)(outh + (size_t)row * D_MODEL))[t] = q;
    }
}

// ---------------------------------------------------------------------------
// Launch — attn_f16 in profiled slot #4
// ---------------------------------------------------------------------------
extern "C" void kernel_launch(void* const* d_in, const int* in_sizes, int n_in,
                              void* d_out, int out_size)
{
    const float* x    = (const float*)d_in[0];
    const int*   mask = (const int*)  d_in[1];
    const float* wq   = (const float*)d_in[2];
    const float* bq   = (const float*)d_in[3];
    const float* wk   = (const float*)d_in[4];
    const float* bk   = (const float*)d_in[5];
    const float* wv   = (const float*)d_in[6];
    const float* bv   = (const float*)d_in[7];
    const float* wo   = (const float*)d_in[8];
    const float* bo   = (const float*)d_in[9];
    const float* w1   = (const float*)d_in[10];
    const float* b1   = (const float*)d_in[11];
    const float* w2   = (const float*)d_in[12];
    const float* b2   = (const float*)d_in[13];
    const float* ln1g = (const float*)d_in[14];
    const float* ln1b = (const float*)d_in[15];
    const float* ln2g = (const float*)d_in[16];
    const float* ln2b = (const float*)d_in[17];

    __half *xh, *qkv, *ap, *x1h, *f1p;
    float *pp, *x1p, *f2p, *bqkv;
    __half *wqkvt, *wot, *w1t, *w2t;
    cudaGetSymbolAddress((void**)&xh,    g_xh);
    cudaGetSymbolAddress((void**)&qkv,   g_qkv);
    cudaGetSymbolAddress((void**)&ap,    g_attn);
    cudaGetSymbolAddress((void**)&pp,    g_proj);
    cudaGetSymbolAddress((void**)&x1p,   g_x1);
    cudaGetSymbolAddress((void**)&x1h,   g_x1h);
    cudaGetSymbolAddress((void**)&f1p,   g_ff1);
    cudaGetSymbolAddress((void**)&f2p,   g_ff2);
    cudaGetSymbolAddress((void**)&wqkvt, g_wqkvt);
    cudaGetSymbolAddress((void**)&wot,   g_wot);
    cudaGetSymbolAddress((void**)&w1t,   g_w1t);
    cudaGetSymbolAddress((void**)&w2t,   g_w2t);
    cudaGetSymbolAddress((void**)&bqkv,  g_bqkv);

    static int attr_set = 0;
    if (!attr_set) {
        cudaFuncSetAttribute(gemm_f16,
                             cudaFuncAttributeMaxDynamicSharedMemorySize,
                             GEMM_SMEM_BYTES);
        cudaFuncSetAttribute(gemm_f16,
                             cudaFuncAttributePreferredSharedMemoryCarveout,
                             cudaSharedmemCarveoutMaxShared);
        attr_set = 1;
    }

    // 1-2: QKV GEMM dependencies
    prep_kernel<<<2060, 256>>>(x, xh, bq, bk, bv, bqkv);
    transpose3_kernel<<<dim3(32, 32, 3), 256>>>(wq, wk, wv, wqkvt);

    // 3: fused QKV GEMM
    gemm_f16<<<dim3(QKV_N / 128, ROWS / 128), 128, GEMM_SMEM_BYTES>>>(
        xh, wqkvt, bqkv, qkv, D_MODEL, QKV_N, 2);

    // 4 (profiled): attention — 128 q-rows per CTA
    attn_f16<<<dim3(S_ / 128, NUM_HEADS, B_), 128>>>(qkv, mask, ap);

    transpose_h_kernel<<<dim3(D_MODEL / 32, D_MODEL / 32), 256>>>(wo, wot, D_MODEL, D_MODEL);
    transpose_h_kernel<<<dim3(D_FF / 32,    D_MODEL / 32), 256>>>(w1, w1t, D_MODEL, D_FF);
    transpose_h_kernel<<<dim3(D_MODEL / 32, D_FF / 32),    256>>>(w2, w2t, D_FF, D_MODEL);

    gemm_f16<<<dim3(D_MODEL / 128, ROWS / 128), 128, GEMM_SMEM_BYTES>>>(
        ap, wot, bo, pp, D_MODEL, D_MODEL, 0);
    add_ln_kernel<<<ROWS, 256>>>(x, pp, ln1g, ln1b, x1p, x1h);

    gemm_f16<<<dim3(D_FF / 128, ROWS / 128), 128, GEMM_SMEM_BYTES>>>(
        x1h, w1t, b1, f1p, D_MODEL, D_FF, 1);
    gemm_f16<<<dim3(D_MODEL / 128, ROWS / 128), 128, GEMM_SMEM_BYTES>>>(
        f1p, w2t, b2, f2p, D_FF, D_MODEL, 0);
    add_ln_kernel<<<ROWS, 256>>>(x1p, f2p, ln2g, ln2b, (float*)d_out, (__half*)0);
}